// round 10
// baseline (speedup 1.0000x reference)
#include <cuda_runtime.h>
#include <cuda_bf16.h>
#include <math.h>
#include <stdint.h>

#define NNODES 10000
#define NEDGES 100000
#define NH     3
#define CH     1024
#define HC     3072          /* NH*CH */
#define ET     110000        /* NEDGES + NNODES self loops */
#define NCLS   460
#define FIN    1024
#define TILE   32

// ------------------------- scratch (device globals, no allocs) -------------
__device__ float g_xl[(size_t)NNODES * HC];
__device__ float g_xr[(size_t)NNODES * HC];
__device__ float g_hmean[(size_t)NNODES * CH];
__device__ int   g_count[NNODES];
__device__ int   g_rowstart[NNODES + 1];
__device__ int   g_cursor[NNODES];
__device__ int   g_csr[ET];                      // stores SRC node per slot
// bf16 hi/lo splits
__device__ __nv_bfloat16 g_xhi[(size_t)NNODES * FIN];
__device__ __nv_bfloat16 g_xlo[(size_t)NNODES * FIN];
__device__ __nv_bfloat16 g_wlThi[(size_t)HC * FIN];   // Wl^T [N=HC][K=FIN]
__device__ __nv_bfloat16 g_wlTlo[(size_t)HC * FIN];
__device__ __nv_bfloat16 g_wrThi[(size_t)HC * FIN];
__device__ __nv_bfloat16 g_wrTlo[(size_t)HC * FIN];
__device__ __nv_bfloat16 g_hmhi[(size_t)NNODES * CH];
__device__ __nv_bfloat16 g_hmlo[(size_t)NNODES * CH];
__device__ __nv_bfloat16 g_wfcThi[(size_t)512 * CH];  // Wfc^T padded rows
__device__ __nv_bfloat16 g_wfcTlo[(size_t)512 * CH];

// ------------------------- split/transpose prep -----------------------------
__global__ void x_split(const float* __restrict__ x)
{
    int i = blockIdx.x * blockDim.x + threadIdx.x;
    if (i >= NNODES * FIN) return;
    float v = x[i];
    __nv_bfloat16 hi = __float2bfloat16_rn(v);
    float lo = v - __bfloat162float(hi);
    g_xhi[i] = hi;
    g_xlo[i] = __float2bfloat16_rn(lo);
}

__global__ void hm_split()
{
    int i = blockIdx.x * blockDim.x + threadIdx.x;
    if (i >= NNODES * CH) return;
    float v = g_hmean[i];
    __nv_bfloat16 hi = __float2bfloat16_rn(v);
    float lo = v - __bfloat162float(hi);
    g_hmhi[i] = hi;
    g_hmlo[i] = __float2bfloat16_rn(lo);
}

// W [K][Ntot] -> T hi/lo [Ntot][K]  (generalized, clamped)
__global__ __launch_bounds__(256) void w_splitT_g(
    const float* __restrict__ W, __nv_bfloat16* __restrict__ Thi,
    __nv_bfloat16* __restrict__ Tlo, int Ntot, int K)
{
    __shared__ float tile[32][33];
    int tx = threadIdx.x & 31;
    int ty = threadIdx.x >> 5;
    int n0 = blockIdx.x * 32;
    int k0 = blockIdx.y * 32;
#pragma unroll
    for (int i = ty; i < 32; i += 8) {
        float v = 0.f;
        if (n0 + tx < Ntot) v = W[(size_t)(k0 + i) * Ntot + n0 + tx];
        tile[i][tx] = v;
    }
    __syncthreads();
#pragma unroll
    for (int i = ty; i < 32; i += 8) {
        if (n0 + i < Ntot) {
            float v = tile[tx][i];
            __nv_bfloat16 hi = __float2bfloat16_rn(v);
            float lo = v - __bfloat162float(hi);
            size_t o = (size_t)(n0 + i) * K + k0 + tx;
            Thi[o] = hi;
            Tlo[o] = __float2bfloat16_rn(lo);
        }
    }
}

// ------------------------- HMMA bf16-split GEMM ------------------------------
#define KC       32
#define NCHUNK   (FIN / KC)        /* 32 */
#define STRIDE   20                /* uint32 per smem row (16 data + 4 pad) */
#define BUF_U32  (128 * STRIDE)
#define OFF_AHI  0
#define OFF_ALO  (1 * BUF_U32)
#define OFF_BHI  (2 * BUF_U32)
#define OFF_BLO  (3 * BUF_U32)
#define STAGE_U32 (4 * BUF_U32)
#define GEMM_SMEM (2 * STAGE_U32 * 4)   /* 81920 B */

__device__ __forceinline__ uint32_t smem_u32(const void* p) {
    uint32_t a;
    asm("{ .reg .u64 t; cvta.to.shared.u64 t, %1; cvt.u32.u64 %0, t; }"
        : "=r"(a) : "l"(p));
    return a;
}
__device__ __forceinline__ void cp16(uint32_t saddr, const void* g, int src_sz) {
    asm volatile("cp.async.cg.shared.global [%0], [%1], 16, %2;"
                 :: "r"(saddr), "l"(g), "r"(src_sz));
}
__device__ __forceinline__ void ldm_x4(uint32_t& r0, uint32_t& r1,
                                       uint32_t& r2, uint32_t& r3, uint32_t addr) {
    asm volatile("ldmatrix.sync.aligned.m8n8.x4.shared.b16 {%0,%1,%2,%3}, [%4];"
                 : "=r"(r0), "=r"(r1), "=r"(r2), "=r"(r3) : "r"(addr));
}
__device__ __forceinline__ void mma_bf16(float& c0, float& c1, float& c2, float& c3,
                                         uint32_t a0, uint32_t a1, uint32_t a2,
                                         uint32_t a3, uint32_t b0, uint32_t b1) {
    asm volatile(
        "mma.sync.aligned.m16n8k16.row.col.f32.bf16.bf16.f32 "
        "{%0,%1,%2,%3}, {%4,%5,%6,%7}, {%8,%9}, {%0,%1,%2,%3};"
        : "+f"(c0), "+f"(c1), "+f"(c2), "+f"(c3)
        : "r"(a0), "r"(a1), "r"(a2), "r"(a3), "r"(b0), "r"(b1));
}

// C[M x Nn] (row stride ldC) = A[M x FIN] @ BT[Nn x FIN]^T + bias[Nn]
__global__ __launch_bounds__(256) void gemm_mma(
    const __nv_bfloat16* __restrict__ Ahi, const __nv_bfloat16* __restrict__ Alo,
    const __nv_bfloat16* __restrict__ BThi, const __nv_bfloat16* __restrict__ BTlo,
    const float* __restrict__ bias, float* __restrict__ C,
    int M, int Nn, int ldC)
{
    extern __shared__ uint32_t smem[];
    const uint32_t sbase = smem_u32(smem);
    const int t = threadIdx.x;
    const int w = t >> 5;
    const int lane = t & 31;
    const int gid = lane >> 2;
    const int tg  = lane & 3;
    const int warpM = w & 1;
    const int warpN = w >> 1;
    const int rowBase = blockIdx.y * 128;
    const int colBase = blockIdx.x * 128;

    const int a_row = (lane & 7) + ((lane >> 3) & 1) * 8;
    const int a_kh  = (lane >> 4) & 1;
    const int b_row = (lane & 7) + ((lane >> 4) & 1) * 8;
    const int b_kh  = (lane >> 3) & 1;

    auto issue = [&](int c, int s) {
        const int k0 = c * KC;
        const uint32_t base = sbase + s * (STAGE_U32 * 4);
#pragma unroll
        for (int i = 0; i < 2; i++) {
            int idx = t + i * 256;
            int row = idx >> 2;
            int q   = idx & 3;
            uint32_t soff = (uint32_t)(row * STRIDE + q * 4) * 4;
            int ar = rowBase + row;
            int ok = (ar < M) ? 16 : 0;
            int arc = (ar < M) ? ar : 0;
            size_t ga = (size_t)arc * FIN + k0 + q * 8;
            cp16(base + OFF_AHI * 4 + soff, Ahi + ga, ok);
            cp16(base + OFF_ALO * 4 + soff, Alo + ga, ok);
            int br = colBase + row;
            int okb = (br < Nn) ? 16 : 0;
            int brc = (br < Nn) ? br : 0;
            size_t gb = (size_t)brc * FIN + k0 + q * 8;
            cp16(base + OFF_BHI * 4 + soff, BThi + gb, okb);
            cp16(base + OFF_BLO * 4 + soff, BTlo + gb, okb);
        }
        asm volatile("cp.async.commit_group;");
    };

    float acc[4][4][4];
#pragma unroll
    for (int mt = 0; mt < 4; mt++)
#pragma unroll
        for (int nt = 0; nt < 4; nt++)
#pragma unroll
            for (int r = 0; r < 4; r++) acc[mt][nt][r] = 0.f;

    issue(0, 0);

    for (int c = 0; c < NCHUNK; c++) {
        if (c + 1 < NCHUNK) {
            issue(c + 1, (c + 1) & 1);
            asm volatile("cp.async.wait_group 1;");
        } else {
            asm volatile("cp.async.wait_group 0;");
        }
        __syncthreads();

        const uint32_t sb = sbase + (c & 1) * (STAGE_U32 * 4);

#pragma unroll
        for (int ks = 0; ks < 2; ks++) {
            uint32_t ah[4][4], al[4][4];
#pragma unroll
            for (int mt = 0; mt < 4; mt++) {
                uint32_t ra = sb + OFF_AHI * 4 +
                    (uint32_t)(((warpM * 64 + mt * 16 + a_row) * STRIDE) +
                               ks * 8 + a_kh * 4) * 4;
                ldm_x4(ah[mt][0], ah[mt][1], ah[mt][2], ah[mt][3], ra);
                ldm_x4(al[mt][0], al[mt][1], al[mt][2], al[mt][3],
                       ra + (OFF_ALO - OFF_AHI) * 4);
            }
            uint32_t bh[4][2], bl[4][2];
#pragma unroll
            for (int ntp = 0; ntp < 2; ntp++) {
                uint32_t rb = sb + OFF_BHI * 4 +
                    (uint32_t)(((warpN * 32 + ntp * 16 + b_row) * STRIDE) +
                               ks * 8 + b_kh * 4) * 4;
                ldm_x4(bh[2 * ntp][0], bh[2 * ntp][1],
                       bh[2 * ntp + 1][0], bh[2 * ntp + 1][1], rb);
                ldm_x4(bl[2 * ntp][0], bl[2 * ntp][1],
                       bl[2 * ntp + 1][0], bl[2 * ntp + 1][1],
                       rb + (OFF_BLO - OFF_BHI) * 4);
            }
#pragma unroll
            for (int nt = 0; nt < 4; nt++) {
#pragma unroll
                for (int mt = 0; mt < 4; mt++) {
                    float* cc = acc[mt][nt];
                    mma_bf16(cc[0], cc[1], cc[2], cc[3],
                             ah[mt][0], ah[mt][1], ah[mt][2], ah[mt][3],
                             bh[nt][0], bh[nt][1]);
                    mma_bf16(cc[0], cc[1], cc[2], cc[3],
                             ah[mt][0], ah[mt][1], ah[mt][2], ah[mt][3],
                             bl[nt][0], bl[nt][1]);
                    mma_bf16(cc[0], cc[1], cc[2], cc[3],
                             al[mt][0], al[mt][1], al[mt][2], al[mt][3],
                             bh[nt][0], bh[nt][1]);
                }
            }
        }
        __syncthreads();
    }

#pragma unroll
    for (int mt = 0; mt < 4; mt++) {
        int r0 = rowBase + warpM * 64 + mt * 16 + gid;
        int r1 = r0 + 8;
#pragma unroll
        for (int nt = 0; nt < 4; nt++) {
            int cb = colBase + warpN * 32 + nt * 8 + tg * 2;
            if (cb >= Nn) continue;
            float b0 = bias[cb], b1 = bias[cb + 1];
            if (r0 < M) {
                float2 o = make_float2(acc[mt][nt][0] + b0, acc[mt][nt][1] + b1);
                *(float2*)(C + (size_t)r0 * ldC + cb) = o;
            }
            if (r1 < M) {
                float2 o = make_float2(acc[mt][nt][2] + b0, acc[mt][nt][3] + b1);
                *(float2*)(C + (size_t)r1 * ldC + cb) = o;
            }
        }
    }
}

// ------------------------- CSR build ---------------------------------------
__global__ void k_zero_counts()
{
    int i = blockIdx.x * blockDim.x + threadIdx.x;
    if (i < NNODES) g_count[i] = 0;
}
__global__ void k_count(const int* __restrict__ ei)
{
    int e = blockIdx.x * blockDim.x + threadIdx.x;
    if (e >= ET) return;
    int dst = (e < NEDGES) ? ei[2 * e + 1] : (e - NEDGES);
    atomicAdd(&g_count[dst], 1);
}
__global__ __launch_bounds__(1024) void k_scan()
{
    __shared__ int sh[1024];
    __shared__ int carry;
    int tid = threadIdx.x;
    if (tid == 0) carry = 0;
    __syncthreads();
    for (int base = 0; base < NNODES; base += 1024) {
        int i = base + tid;
        int v = (i < NNODES) ? g_count[i] : 0;
        sh[tid] = v;
        __syncthreads();
        for (int off = 1; off < 1024; off <<= 1) {
            int t = (tid >= off) ? sh[tid - off] : 0;
            __syncthreads();
            sh[tid] += t;
            __syncthreads();
        }
        int excl = carry + sh[tid] - v;
        if (i < NNODES) { g_rowstart[i] = excl; g_cursor[i] = excl; }
        __syncthreads();
        if (tid == 1023) carry += sh[1023];
        __syncthreads();
    }
    if (tid == 0) g_rowstart[NNODES] = carry;
}
__global__ void k_scatter(const int* __restrict__ ei)
{
    int e = blockIdx.x * blockDim.x + threadIdx.x;
    if (e >= ET) return;
    int src, dst;
    if (e < NEDGES) { src = ei[2 * e]; dst = ei[2 * e + 1]; }
    else            { src = dst = e - NEDGES; }
    int pos = atomicAdd(&g_cursor[dst], 1);
    g_csr[pos] = src;
}

// ------------------------- fused scores + softmax + aggregate ---------------
// One block per destination node; edges processed in tiles of 32.
// Phase A: warp-per-edge scores (no block syncs). Tile-level online softmax
// (numerically identical to per-edge online: same max, same rescales).
// Phase B: per-thread channel aggregation with known tile weights (xl L2-hot).
__global__ __launch_bounds__(128) void node_fused(
    const float* __restrict__ att, const float* __restrict__ bias)
{
    __shared__ float4 satt[HC / 4];      // 12 KB
    __shared__ float4 sxr[HC / 4];       // 12 KB
    __shared__ float  ssc[TILE][NH];
    __shared__ float  swgt[TILE][NH];
    __shared__ int    ssrc[TILE];

    const int node = blockIdx.x;
    const int t = threadIdx.x;
    const int w = t >> 5;
    const int lane = t & 31;

    {
        const float4* xrp = (const float4*)(g_xr + (size_t)node * HC);
        for (int i = t; i < HC / 4; i += 128) {
            satt[i] = ((const float4*)att)[i];
            sxr[i]  = xrp[i];
        }
    }
    __syncthreads();

    const int beg = g_rowstart[node];
    const int end = g_rowstart[node + 1];

    float m[NH], d[NH];
    float4 acc[NH][2];
#pragma unroll
    for (int h = 0; h < NH; h++) {
        m[h] = -3.0e38f;
        d[h] = 0.f;
#pragma unroll
        for (int q = 0; q < 2; q++) acc[h][q] = make_float4(0.f, 0.f, 0.f, 0.f);
    }

    for (int t0 = beg; t0 < end; t0 += TILE) {
        const int tn = min(TILE, end - t0);

        // ---- Phase A: scores, warp-per-edge ----
        for (int p = w; p < tn; p += 4) {
            int src = g_csr[t0 + p];
            if (lane == 0) ssrc[p] = src;
            const float4* xlp = (const float4*)(g_xl + (size_t)src * HC);
            float part[NH];
#pragma unroll
            for (int h = 0; h < NH; h++) {
                part[h] = 0.f;
                for (int i = lane; i < 256; i += 32) {
                    float4 v = xlp[h * 256 + i];
                    float4 r = sxr[h * 256 + i];
                    float4 a = satt[h * 256 + i];
                    float sx = v.x + r.x; sx = sx > 0.f ? sx : 0.2f * sx;
                    float sy = v.y + r.y; sy = sy > 0.f ? sy : 0.2f * sy;
                    float sz = v.z + r.z; sz = sz > 0.f ? sz : 0.2f * sz;
                    float sw = v.w + r.w; sw = sw > 0.f ? sw : 0.2f * sw;
                    part[h] += sx * a.x + sy * a.y + sz * a.z + sw * a.w;
                }
            }
#pragma unroll
            for (int off = 16; off; off >>= 1)
#pragma unroll
                for (int h = 0; h < NH; h++)
                    part[h] += __shfl_xor_sync(0xFFFFFFFFu, part[h], off);
            if (lane == 0)
#pragma unroll
                for (int h = 0; h < NH; h++) ssc[p][h] = part[h];
        }
        __syncthreads();

        // ---- tile max + rescale (deterministic, redundant per thread) ----
        float mt[NH];
#pragma unroll
        for (int h = 0; h < NH; h++) {
            mt[h] = m[h];
            for (int e = 0; e < tn; e++) mt[h] = fmaxf(mt[h], ssc[e][h]);
        }
#pragma unroll
        for (int h = 0; h < NH; h++) {
            float r = __expf(m[h] - mt[h]);     // 0 on first tile
            d[h] *= r;
#pragma unroll
            for (int q = 0; q < 2; q++) {
                acc[h][q].x *= r; acc[h][q].y *= r;
                acc[h][q].z *= r; acc[h][q].w *= r;
            }
            m[h] = mt[h];
        }
        // cooperative weights
        if (t < NH * TILE) {
            int e = t & (TILE - 1);
            int h = t >> 5;
            if (e < tn) swgt[e][h] = __expf(ssc[e][h] - mt[h]);
        }
        __syncthreads();

        // ---- Phase B: aggregation with known weights ----
        for (int e = 0; e < tn; e++) {
            int src = ssrc[e];
            const float4* xlp = (const float4*)(g_xl + (size_t)src * HC);
            float we[NH];
#pragma unroll
            for (int h = 0; h < NH; h++) { we[h] = swgt[e][h]; d[h] += we[h]; }
#pragma unroll
            for (int h = 0; h < NH; h++) {
#pragma unroll
                for (int q = 0; q < 2; q++) {
                    float4 v = xlp[h * 256 + t + 128 * q];
                    acc[h][q].x += we[h] * v.x;
                    acc[h][q].y += we[h] * v.y;
                    acc[h][q].z += we[h] * v.z;
                    acc[h][q].w += we[h] * v.w;
                }
            }
        }
        __syncthreads();   // protect ssc/swgt/ssrc before next tile
    }

    float invd[NH];
#pragma unroll
    for (int h = 0; h < NH; h++) invd[h] = 1.f / (d[h] + 1e-16f);

    const float inv3 = 1.0f / 3.0f;
#pragma unroll
    for (int q = 0; q < 2; q++) {
        int f = t + 128 * q;
        float4 o;
        o.x = (acc[0][q].x * invd[0] + acc[1][q].x * invd[1] + acc[2][q].x * invd[2]) * inv3 + bias[4 * f + 0];
        o.y = (acc[0][q].y * invd[0] + acc[1][q].y * invd[1] + acc[2][q].y * invd[2]) * inv3 + bias[4 * f + 1];
        o.z = (acc[0][q].z * invd[0] + acc[1][q].z * invd[1] + acc[2][q].z * invd[2]) * inv3 + bias[4 * f + 2];
        o.w = (acc[0][q].w * invd[0] + acc[1][q].w * invd[1] + acc[2][q].w * invd[2]) * inv3 + bias[4 * f + 3];
        *(float4*)(g_hmean + (size_t)node * CH + 4 * f) = o;
    }
}

// ------------------------- pass-through copy --------------------------------
__global__ void k_copy4(const float4* __restrict__ src, float4* __restrict__ dst,
                        int n4)
{
    int i = blockIdx.x * blockDim.x + threadIdx.x;
    if (i < n4) dst[i] = src[i];
}

// ------------------------- launch ------------------------------------------
extern "C" void kernel_launch(void* const* d_in, const int* in_sizes, int n_in,
                              void* d_out, int out_size)
{
    const float* x    = (const float*)d_in[0];
    const int*   ei   = (const int*)d_in[1];
    const float* Wl   = (const float*)d_in[2];
    const float* bl   = (const float*)d_in[3];
    const float* Wr   = (const float*)d_in[4];
    const float* br   = (const float*)d_in[5];
    const float* att  = (const float*)d_in[6];
    const float* bias = (const float*)d_in[7];
    const float* Wfc  = (const float*)d_in[8];
    const float* bfc  = (const float*)d_in[9];
    const float* exps   = (const float*)d_in[10];
    const float* exps_c = (const float*)d_in[11];
    float* out = (float*)d_out;

    cudaFuncSetAttribute(gemm_mma, cudaFuncAttributeMaxDynamicSharedMemorySize,
                         GEMM_SMEM);

    // device addresses (NOT host shadow symbols — GB300 ATS trap)
    float *pxl, *pxr;
    __nv_bfloat16 *pxhi, *pxlo, *plThi, *plTlo, *prThi, *prTlo;
    __nv_bfloat16 *phmhi, *phmlo, *pfcThi, *pfcTlo;
    cudaGetSymbolAddress((void**)&pxl,    g_xl);
    cudaGetSymbolAddress((void**)&pxr,    g_xr);
    cudaGetSymbolAddress((void**)&pxhi,   g_xhi);
    cudaGetSymbolAddress((void**)&pxlo,   g_xlo);
    cudaGetSymbolAddress((void**)&plThi,  g_wlThi);
    cudaGetSymbolAddress((void**)&plTlo,  g_wlTlo);
    cudaGetSymbolAddress((void**)&prThi,  g_wrThi);
    cudaGetSymbolAddress((void**)&prTlo,  g_wrTlo);
    cudaGetSymbolAddress((void**)&phmhi,  g_hmhi);
    cudaGetSymbolAddress((void**)&phmlo,  g_hmlo);
    cudaGetSymbolAddress((void**)&pfcThi, g_wfcThi);
    cudaGetSymbolAddress((void**)&pfcTlo, g_wfcTlo);

    // bf16 hi/lo splits of x and W^T
    x_split<<<(NNODES * FIN + 255) / 256, 256>>>(x);
    {
        dim3 grid(HC / 32, FIN / 32);
        w_splitT_g<<<grid, 256>>>(Wl, plThi, plTlo, HC, FIN);
        w_splitT_g<<<grid, 256>>>(Wr, prThi, prTlo, HC, FIN);
    }
    {
        dim3 grid((NCLS + 31) / 32, CH / 32);
        w_splitT_g<<<grid, 256>>>(Wfc, pfcThi, pfcTlo, NCLS, CH);
    }

    // projections on tensor cores
    {
        dim3 grid(HC / 128, (NNODES + 127) / 128);
        gemm_mma<<<grid, 256, GEMM_SMEM>>>(pxhi, pxlo, plThi, plTlo,
                                           bl, pxl, NNODES, HC, HC);
        gemm_mma<<<grid, 256, GEMM_SMEM>>>(pxhi, pxlo, prThi, prTlo,
                                           br, pxr, NNODES, HC, HC);
    }

    // CSR by destination
    k_zero_counts<<<(NNODES + 255) / 256, 256>>>();
    k_count<<<(ET + 255) / 256, 256>>>(ei);
    k_scan<<<1, 1024>>>();
    k_scatter<<<(ET + 255) / 256, 256>>>(ei);

    // fused scores + tiled online softmax + aggregation + head mean + bias
    node_fused<<<NNODES, 128>>>(att, bias);

    // fc readout on tensor cores
    hm_split<<<(NNODES * CH + 255) / 256, 256>>>();
    {
        dim3 grid((NCLS + 127) / 128, (NNODES + 127) / 128);
        gemm_mma<<<grid, 256, GEMM_SMEM>>>(phmhi, phmlo, pfcThi, pfcTlo,
                                           bfc, out, NNODES, NCLS, NCLS);
    }

    // pass-through outputs
    size_t hElems = (size_t)NNODES * NCLS;
    int n4a = in_sizes[10] / 4;
    int n4b = in_sizes[11] / 4;
    k_copy4<<<(n4a + 255) / 256, 256>>>((const float4*)exps,
                                        (float4*)(out + hElems), n4a);
    k_copy4<<<(n4b + 255) / 256, 256>>>((const float4*)exps_c,
                                        (float4*)(out + hElems + in_sizes[10]), n4b);
}

// round 11
// speedup vs baseline: 1.0651x; 1.0651x over previous
#include <cuda_runtime.h>
#include <cuda_bf16.h>
#include <math.h>
#include <stdint.h>

#define NNODES 10000
#define NEDGES 100000
#define NH     3
#define CH     1024
#define HC     3072          /* NH*CH */
#define ET     110000        /* NEDGES + NNODES self loops */
#define NCLS   460
#define FIN    1024

// ------------------------- scratch (device globals, no allocs) -------------
__device__ float g_xl[(size_t)NNODES * HC];
__device__ float g_xr[(size_t)NNODES * HC];
__device__ int   g_count[NNODES];
__device__ int   g_rowstart[NNODES + 1];
__device__ int   g_cursor[NNODES];
__device__ int   g_csr[ET];                      // stores SRC node per slot
// bf16 hi/lo splits
__device__ __nv_bfloat16 g_xhi[(size_t)NNODES * FIN];
__device__ __nv_bfloat16 g_xlo[(size_t)NNODES * FIN];
__device__ __nv_bfloat16 g_wlThi[(size_t)HC * FIN];   // Wl^T [N=HC][K=FIN]
__device__ __nv_bfloat16 g_wlTlo[(size_t)HC * FIN];
__device__ __nv_bfloat16 g_wrThi[(size_t)HC * FIN];
__device__ __nv_bfloat16 g_wrTlo[(size_t)HC * FIN];
__device__ __nv_bfloat16 g_hmhi[(size_t)NNODES * CH];
__device__ __nv_bfloat16 g_hmlo[(size_t)NNODES * CH];
__device__ __nv_bfloat16 g_wfcThi[(size_t)512 * CH];  // Wfc^T padded rows
__device__ __nv_bfloat16 g_wfcTlo[(size_t)512 * CH];

// ------------------------- split/transpose prep -----------------------------
__global__ void x_split(const float* __restrict__ x)
{
    int i = blockIdx.x * blockDim.x + threadIdx.x;
    if (i >= NNODES * FIN) return;
    float v = x[i];
    __nv_bfloat16 hi = __float2bfloat16_rn(v);
    float lo = v - __bfloat162float(hi);
    g_xhi[i] = hi;
    g_xlo[i] = __float2bfloat16_rn(lo);
}

// W [K][Ntot] -> T hi/lo [Ntot][K]  (generalized, clamped)
__global__ __launch_bounds__(256) void w_splitT_g(
    const float* __restrict__ W, __nv_bfloat16* __restrict__ Thi,
    __nv_bfloat16* __restrict__ Tlo, int Ntot, int K)
{
    __shared__ float tile[32][33];
    int tx = threadIdx.x & 31;
    int ty = threadIdx.x >> 5;
    int n0 = blockIdx.x * 32;
    int k0 = blockIdx.y * 32;
#pragma unroll
    for (int i = ty; i < 32; i += 8) {
        float v = 0.f;
        if (n0 + tx < Ntot) v = W[(size_t)(k0 + i) * Ntot + n0 + tx];
        tile[i][tx] = v;
    }
    __syncthreads();
#pragma unroll
    for (int i = ty; i < 32; i += 8) {
        if (n0 + i < Ntot) {
            float v = tile[tx][i];
            __nv_bfloat16 hi = __float2bfloat16_rn(v);
            float lo = v - __bfloat162float(hi);
            size_t o = (size_t)(n0 + i) * K + k0 + tx;
            Thi[o] = hi;
            Tlo[o] = __float2bfloat16_rn(lo);
        }
    }
}

// ------------------------- HMMA bf16-split GEMM ------------------------------
#define KC       32
#define NCHUNK   (FIN / KC)        /* 32 */
#define STRIDE   20                /* uint32 per smem row (16 data + 4 pad) */
#define BUF_U32  (128 * STRIDE)
#define OFF_AHI  0
#define OFF_ALO  (1 * BUF_U32)
#define OFF_BHI  (2 * BUF_U32)
#define OFF_BLO  (3 * BUF_U32)
#define STAGE_U32 (4 * BUF_U32)
#define GEMM_SMEM (2 * STAGE_U32 * 4)   /* 81920 B */

__device__ __forceinline__ uint32_t smem_u32(const void* p) {
    uint32_t a;
    asm("{ .reg .u64 t; cvta.to.shared.u64 t, %1; cvt.u32.u64 %0, t; }"
        : "=r"(a) : "l"(p));
    return a;
}
__device__ __forceinline__ void cp16(uint32_t saddr, const void* g, int src_sz) {
    asm volatile("cp.async.cg.shared.global [%0], [%1], 16, %2;"
                 :: "r"(saddr), "l"(g), "r"(src_sz));
}
__device__ __forceinline__ void ldm_x4(uint32_t& r0, uint32_t& r1,
                                       uint32_t& r2, uint32_t& r3, uint32_t addr) {
    asm volatile("ldmatrix.sync.aligned.m8n8.x4.shared.b16 {%0,%1,%2,%3}, [%4];"
                 : "=r"(r0), "=r"(r1), "=r"(r2), "=r"(r3) : "r"(addr));
}
__device__ __forceinline__ void mma_bf16(float& c0, float& c1, float& c2, float& c3,
                                         uint32_t a0, uint32_t a1, uint32_t a2,
                                         uint32_t a3, uint32_t b0, uint32_t b1) {
    asm volatile(
        "mma.sync.aligned.m16n8k16.row.col.f32.bf16.bf16.f32 "
        "{%0,%1,%2,%3}, {%4,%5,%6,%7}, {%8,%9}, {%0,%1,%2,%3};"
        : "+f"(c0), "+f"(c1), "+f"(c2), "+f"(c3)
        : "r"(a0), "r"(a1), "r"(a2), "r"(a3), "r"(b0), "r"(b1));
}

// C[M x Nn] (row stride ldC) = A[M x FIN] @ BT[Nn x FIN]^T + bias[Nn]
__global__ __launch_bounds__(256) void gemm_mma(
    const __nv_bfloat16* __restrict__ Ahi, const __nv_bfloat16* __restrict__ Alo,
    const __nv_bfloat16* __restrict__ BThi, const __nv_bfloat16* __restrict__ BTlo,
    const float* __restrict__ bias, float* __restrict__ C,
    int M, int Nn, int ldC)
{
    extern __shared__ uint32_t smem[];
    const uint32_t sbase = smem_u32(smem);
    const int t = threadIdx.x;
    const int w = t >> 5;
    const int lane = t & 31;
    const int gid = lane >> 2;
    const int tg  = lane & 3;
    const int warpM = w & 1;
    const int warpN = w >> 1;
    const int rowBase = blockIdx.y * 128;
    const int colBase = blockIdx.x * 128;

    const int a_row = (lane & 7) + ((lane >> 3) & 1) * 8;
    const int a_kh  = (lane >> 4) & 1;
    const int b_row = (lane & 7) + ((lane >> 4) & 1) * 8;
    const int b_kh  = (lane >> 3) & 1;

    auto issue = [&](int c, int s) {
        const int k0 = c * KC;
        const uint32_t base = sbase + s * (STAGE_U32 * 4);
#pragma unroll
        for (int i = 0; i < 2; i++) {
            int idx = t + i * 256;
            int row = idx >> 2;
            int q   = idx & 3;
            uint32_t soff = (uint32_t)(row * STRIDE + q * 4) * 4;
            int ar = rowBase + row;
            int ok = (ar < M) ? 16 : 0;
            int arc = (ar < M) ? ar : 0;
            size_t ga = (size_t)arc * FIN + k0 + q * 8;
            cp16(base + OFF_AHI * 4 + soff, Ahi + ga, ok);
            cp16(base + OFF_ALO * 4 + soff, Alo + ga, ok);
            int br = colBase + row;
            int okb = (br < Nn) ? 16 : 0;
            int brc = (br < Nn) ? br : 0;
            size_t gb = (size_t)brc * FIN + k0 + q * 8;
            cp16(base + OFF_BHI * 4 + soff, BThi + gb, okb);
            cp16(base + OFF_BLO * 4 + soff, BTlo + gb, okb);
        }
        asm volatile("cp.async.commit_group;");
    };

    float acc[4][4][4];
#pragma unroll
    for (int mt = 0; mt < 4; mt++)
#pragma unroll
        for (int nt = 0; nt < 4; nt++)
#pragma unroll
            for (int r = 0; r < 4; r++) acc[mt][nt][r] = 0.f;

    issue(0, 0);

    for (int c = 0; c < NCHUNK; c++) {
        if (c + 1 < NCHUNK) {
            issue(c + 1, (c + 1) & 1);
            asm volatile("cp.async.wait_group 1;");
        } else {
            asm volatile("cp.async.wait_group 0;");
        }
        __syncthreads();

        const uint32_t sb = sbase + (c & 1) * (STAGE_U32 * 4);

#pragma unroll
        for (int ks = 0; ks < 2; ks++) {
            uint32_t ah[4][4], al[4][4];
#pragma unroll
            for (int mt = 0; mt < 4; mt++) {
                uint32_t ra = sb + OFF_AHI * 4 +
                    (uint32_t)(((warpM * 64 + mt * 16 + a_row) * STRIDE) +
                               ks * 8 + a_kh * 4) * 4;
                ldm_x4(ah[mt][0], ah[mt][1], ah[mt][2], ah[mt][3], ra);
                ldm_x4(al[mt][0], al[mt][1], al[mt][2], al[mt][3],
                       ra + (OFF_ALO - OFF_AHI) * 4);
            }
            uint32_t bh[4][2], bl[4][2];
#pragma unroll
            for (int ntp = 0; ntp < 2; ntp++) {
                uint32_t rb = sb + OFF_BHI * 4 +
                    (uint32_t)(((warpN * 32 + ntp * 16 + b_row) * STRIDE) +
                               ks * 8 + b_kh * 4) * 4;
                ldm_x4(bh[2 * ntp][0], bh[2 * ntp][1],
                       bh[2 * ntp + 1][0], bh[2 * ntp + 1][1], rb);
                ldm_x4(bl[2 * ntp][0], bl[2 * ntp][1],
                       bl[2 * ntp + 1][0], bl[2 * ntp + 1][1],
                       rb + (OFF_BLO - OFF_BHI) * 4);
            }
#pragma unroll
            for (int nt = 0; nt < 4; nt++) {
#pragma unroll
                for (int mt = 0; mt < 4; mt++) {
                    float* cc = acc[mt][nt];
                    mma_bf16(cc[0], cc[1], cc[2], cc[3],
                             ah[mt][0], ah[mt][1], ah[mt][2], ah[mt][3],
                             bh[nt][0], bh[nt][1]);
                    mma_bf16(cc[0], cc[1], cc[2], cc[3],
                             ah[mt][0], ah[mt][1], ah[mt][2], ah[mt][3],
                             bl[nt][0], bl[nt][1]);
                    mma_bf16(cc[0], cc[1], cc[2], cc[3],
                             al[mt][0], al[mt][1], al[mt][2], al[mt][3],
                             bh[nt][0], bh[nt][1]);
                }
            }
        }
        __syncthreads();
    }

#pragma unroll
    for (int mt = 0; mt < 4; mt++) {
        int r0 = rowBase + warpM * 64 + mt * 16 + gid;
        int r1 = r0 + 8;
#pragma unroll
        for (int nt = 0; nt < 4; nt++) {
            int cb = colBase + warpN * 32 + nt * 8 + tg * 2;
            if (cb >= Nn) continue;
            float b0 = bias[cb], b1 = bias[cb + 1];
            if (r0 < M) {
                float2 o = make_float2(acc[mt][nt][0] + b0, acc[mt][nt][1] + b1);
                *(float2*)(C + (size_t)r0 * ldC + cb) = o;
            }
            if (r1 < M) {
                float2 o = make_float2(acc[mt][nt][2] + b0, acc[mt][nt][3] + b1);
                *(float2*)(C + (size_t)r1 * ldC + cb) = o;
            }
        }
    }
}

// ------------------------- CSR build ---------------------------------------
__global__ void k_zero_counts()
{
    int i = blockIdx.x * blockDim.x + threadIdx.x;
    if (i < NNODES) g_count[i] = 0;
}
__global__ void k_count(const int* __restrict__ ei)
{
    int e = blockIdx.x * blockDim.x + threadIdx.x;
    if (e >= ET) return;
    int dst = (e < NEDGES) ? ei[2 * e + 1] : (e - NEDGES);
    atomicAdd(&g_count[dst], 1);
}
__global__ __launch_bounds__(1024) void k_scan()
{
    __shared__ int sh[1024];
    __shared__ int carry;
    int tid = threadIdx.x;
    if (tid == 0) carry = 0;
    __syncthreads();
    for (int base = 0; base < NNODES; base += 1024) {
        int i = base + tid;
        int v = (i < NNODES) ? g_count[i] : 0;
        sh[tid] = v;
        __syncthreads();
        for (int off = 1; off < 1024; off <<= 1) {
            int t = (tid >= off) ? sh[tid - off] : 0;
            __syncthreads();
            sh[tid] += t;
            __syncthreads();
        }
        int excl = carry + sh[tid] - v;
        if (i < NNODES) { g_rowstart[i] = excl; g_cursor[i] = excl; }
        __syncthreads();
        if (tid == 1023) carry += sh[1023];
        __syncthreads();
    }
    if (tid == 0) g_rowstart[NNODES] = carry;
}
__global__ void k_scatter(const int* __restrict__ ei)
{
    int e = blockIdx.x * blockDim.x + threadIdx.x;
    if (e >= ET) return;
    int src, dst;
    if (e < NEDGES) { src = ei[2 * e]; dst = ei[2 * e + 1]; }
    else            { src = dst = e - NEDGES; }
    int pos = atomicAdd(&g_cursor[dst], 1);
    g_csr[pos] = src;
}

// ------------------------- fused scores + softmax + aggregate ---------------
// r9 structure (single xl read per edge) + software-pipelined prefetch of the
// next edge's xl row, hiding gather latency under the score reduce barriers.
// Epilogue writes bf16 hi/lo directly (fc GEMM input) — no hm_split pass.
__global__ __launch_bounds__(128) void node_fused(
    const float* __restrict__ att, const float* __restrict__ bias)
{
    __shared__ float4 satt[HC / 4];      // 12 KB
    __shared__ float  red[4][NH];

    const int node = blockIdx.x;
    const int t = threadIdx.x;
    const int w = t >> 5;
    const int lane = t & 31;

    for (int i = t; i < HC / 4; i += 128)
        satt[i] = ((const float4*)att)[i];

    const int beg = g_rowstart[node];
    const int end = g_rowstart[node + 1];

    float4 xr[NH][2];
    {
        const float4* xrp = (const float4*)(g_xr + (size_t)node * HC);
#pragma unroll
        for (int h = 0; h < NH; h++)
#pragma unroll
            for (int q = 0; q < 2; q++)
                xr[h][q] = xrp[h * 256 + t + 128 * q];
    }
    __syncthreads();

    float m[NH], d[NH];
    float4 acc[NH][2];
#pragma unroll
    for (int h = 0; h < NH; h++) {
        m[h] = -3.0e38f;
        d[h] = 0.f;
#pragma unroll
        for (int q = 0; q < 2; q++) acc[h][q] = make_float4(0.f, 0.f, 0.f, 0.f);
    }

    // prologue: load first edge's xl row
    float4 cur[NH][2];
    if (beg < end) {
        const float4* xlp = (const float4*)(g_xl + (size_t)g_csr[beg] * HC);
#pragma unroll
        for (int h = 0; h < NH; h++)
#pragma unroll
            for (int q = 0; q < 2; q++)
                cur[h][q] = xlp[h * 256 + t + 128 * q];
    }

    for (int p = beg; p < end; p++) {
        // prefetch next edge's xl row (loads fly through the barriers below)
        float4 nxt[NH][2];
        if (p + 1 < end) {
            const float4* xln = (const float4*)(g_xl + (size_t)g_csr[p + 1] * HC);
#pragma unroll
            for (int h = 0; h < NH; h++)
#pragma unroll
                for (int q = 0; q < 2; q++)
                    nxt[h][q] = xln[h * 256 + t + 128 * q];
        }

        // score from cur
        float part[NH];
#pragma unroll
        for (int h = 0; h < NH; h++) {
            part[h] = 0.f;
#pragma unroll
            for (int q = 0; q < 2; q++) {
                float4 v = cur[h][q];
                float4 r = xr[h][q];
                float4 a = satt[h * 256 + t + 128 * q];
                float sx = v.x + r.x; sx = sx > 0.f ? sx : 0.2f * sx;
                float sy = v.y + r.y; sy = sy > 0.f ? sy : 0.2f * sy;
                float sz = v.z + r.z; sz = sz > 0.f ? sz : 0.2f * sz;
                float sw = v.w + r.w; sw = sw > 0.f ? sw : 0.2f * sw;
                part[h] += sx * a.x + sy * a.y + sz * a.z + sw * a.w;
            }
        }
#pragma unroll
        for (int off = 16; off; off >>= 1)
#pragma unroll
            for (int h = 0; h < NH; h++)
                part[h] += __shfl_xor_sync(0xFFFFFFFFu, part[h], off);
        if (lane == 0)
#pragma unroll
            for (int h = 0; h < NH; h++) red[w][h] = part[h];
        __syncthreads();

        float s[NH];
#pragma unroll
        for (int h = 0; h < NH; h++)
            s[h] = red[0][h] + red[1][h] + red[2][h] + red[3][h];
        __syncthreads();

#pragma unroll
        for (int h = 0; h < NH; h++) {
            float e;
            if (s[h] > m[h]) {
                float sc = __expf(m[h] - s[h]);
                d[h] *= sc;
#pragma unroll
                for (int q = 0; q < 2; q++) {
                    acc[h][q].x *= sc; acc[h][q].y *= sc;
                    acc[h][q].z *= sc; acc[h][q].w *= sc;
                }
                m[h] = s[h];
                e = 1.f;
            } else {
                e = __expf(s[h] - m[h]);
            }
            d[h] += e;
#pragma unroll
            for (int q = 0; q < 2; q++) {
                acc[h][q].x += e * cur[h][q].x;
                acc[h][q].y += e * cur[h][q].y;
                acc[h][q].z += e * cur[h][q].z;
                acc[h][q].w += e * cur[h][q].w;
            }
        }

        if (p + 1 < end) {
#pragma unroll
            for (int h = 0; h < NH; h++)
#pragma unroll
                for (int q = 0; q < 2; q++)
                    cur[h][q] = nxt[h][q];
        }
    }

    float invd[NH];
#pragma unroll
    for (int h = 0; h < NH; h++) invd[h] = 1.f / (d[h] + 1e-16f);

    const float inv3 = 1.0f / 3.0f;
#pragma unroll
    for (int q = 0; q < 2; q++) {
        int f = t + 128 * q;
        float o[4];
        o[0] = (acc[0][q].x * invd[0] + acc[1][q].x * invd[1] + acc[2][q].x * invd[2]) * inv3 + bias[4 * f + 0];
        o[1] = (acc[0][q].y * invd[0] + acc[1][q].y * invd[1] + acc[2][q].y * invd[2]) * inv3 + bias[4 * f + 1];
        o[2] = (acc[0][q].z * invd[0] + acc[1][q].z * invd[1] + acc[2][q].z * invd[2]) * inv3 + bias[4 * f + 2];
        o[3] = (acc[0][q].w * invd[0] + acc[1][q].w * invd[1] + acc[2][q].w * invd[2]) * inv3 + bias[4 * f + 3];
        // fused bf16 hi/lo split (feeds fc HMMA GEMM directly)
        __nv_bfloat16 hi[4], lo[4];
#pragma unroll
        for (int j = 0; j < 4; j++) {
            hi[j] = __float2bfloat16_rn(o[j]);
            lo[j] = __float2bfloat16_rn(o[j] - __bfloat162float(hi[j]));
        }
        size_t idx = (size_t)node * CH + 4 * f;
        *(uint2*)(g_hmhi + idx) = *(uint2*)hi;
        *(uint2*)(g_hmlo + idx) = *(uint2*)lo;
    }
}

// ------------------------- pass-through copy --------------------------------
__global__ void k_copy4(const float4* __restrict__ src, float4* __restrict__ dst,
                        int n4)
{
    int i = blockIdx.x * blockDim.x + threadIdx.x;
    if (i < n4) dst[i] = src[i];
}

// ------------------------- launch ------------------------------------------
extern "C" void kernel_launch(void* const* d_in, const int* in_sizes, int n_in,
                              void* d_out, int out_size)
{
    const float* x    = (const float*)d_in[0];
    const int*   ei   = (const int*)d_in[1];
    const float* Wl   = (const float*)d_in[2];
    const float* bl   = (const float*)d_in[3];
    const float* Wr   = (const float*)d_in[4];
    const float* br   = (const float*)d_in[5];
    const float* att  = (const float*)d_in[6];
    const float* bias = (const float*)d_in[7];
    const float* Wfc  = (const float*)d_in[8];
    const float* bfc  = (const float*)d_in[9];
    const float* exps   = (const float*)d_in[10];
    const float* exps_c = (const float*)d_in[11];
    float* out = (float*)d_out;

    cudaFuncSetAttribute(gemm_mma, cudaFuncAttributeMaxDynamicSharedMemorySize,
                         GEMM_SMEM);

    // device addresses (NOT host shadow symbols — GB300 ATS trap)
    float *pxl, *pxr;
    __nv_bfloat16 *pxhi, *pxlo, *plThi, *plTlo, *prThi, *prTlo;
    __nv_bfloat16 *phmhi, *phmlo, *pfcThi, *pfcTlo;
    cudaGetSymbolAddress((void**)&pxl,    g_xl);
    cudaGetSymbolAddress((void**)&pxr,    g_xr);
    cudaGetSymbolAddress((void**)&pxhi,   g_xhi);
    cudaGetSymbolAddress((void**)&pxlo,   g_xlo);
    cudaGetSymbolAddress((void**)&plThi,  g_wlThi);
    cudaGetSymbolAddress((void**)&plTlo,  g_wlTlo);
    cudaGetSymbolAddress((void**)&prThi,  g_wrThi);
    cudaGetSymbolAddress((void**)&prTlo,  g_wrTlo);
    cudaGetSymbolAddress((void**)&phmhi,  g_hmhi);
    cudaGetSymbolAddress((void**)&phmlo,  g_hmlo);
    cudaGetSymbolAddress((void**)&pfcThi, g_wfcThi);
    cudaGetSymbolAddress((void**)&pfcTlo, g_wfcTlo);

    // bf16 hi/lo splits of x and W^T
    x_split<<<(NNODES * FIN + 255) / 256, 256>>>(x);
    {
        dim3 grid(HC / 32, FIN / 32);
        w_splitT_g<<<grid, 256>>>(Wl, plThi, plTlo, HC, FIN);
        w_splitT_g<<<grid, 256>>>(Wr, prThi, prTlo, HC, FIN);
    }
    {
        dim3 grid((NCLS + 31) / 32, CH / 32);
        w_splitT_g<<<grid, 256>>>(Wfc, pfcThi, pfcTlo, NCLS, CH);
    }

    // projections on tensor cores
    {
        dim3 grid(HC / 128, (NNODES + 127) / 128);
        gemm_mma<<<grid, 256, GEMM_SMEM>>>(pxhi, pxlo, plThi, plTlo,
                                           bl, pxl, NNODES, HC, HC);
        gemm_mma<<<grid, 256, GEMM_SMEM>>>(pxhi, pxlo, prThi, prTlo,
                                           br, pxr, NNODES, HC, HC);
    }

    // CSR by destination
    k_zero_counts<<<(NNODES + 255) / 256, 256>>>();
    k_count<<<(ET + 255) / 256, 256>>>(ei);
    k_scan<<<1, 1024>>>();
    k_scatter<<<(ET + 255) / 256, 256>>>(ei);

    // fused scores + online softmax + aggregation + head mean + bias
    // (writes bf16 hi/lo directly for the fc GEMM)
    node_fused<<<NNODES, 128>>>(att, bias);

    // fc readout on tensor cores
    {
        dim3 grid((NCLS + 127) / 128, (NNODES + 127) / 128);
        gemm_mma<<<grid, 256, GEMM_SMEM>>>(phmhi, phmlo, pfcThi, pfcTlo,
                                           bfc, out, NNODES, NCLS, NCLS);
    }

    // pass-through outputs
    size_t hElems = (size_t)NNODES * NCLS;
    int n4a = in_sizes[10] / 4;
    int n4b = in_sizes[11] / 4;
    k_copy4<<<(n4a + 255) / 256, 256>>>((const float4*)exps,
                                        (float4*)(out + hElems), n4a);
    k_copy4<<<(n4b + 255) / 256, 256>>>((const float4*)exps_c,
                                        (float4*)(out + hElems + in_sizes[10]), n4b);
}

// round 12
// speedup vs baseline: 1.1024x; 1.0351x over previous
#include <cuda_runtime.h>
#include <cuda_bf16.h>
#include <math.h>
#include <stdint.h>

#define NNODES 10000
#define NEDGES 100000
#define NH     3
#define CH     1024
#define HC     3072          /* NH*CH */
#define ET     110000        /* NEDGES + NNODES self loops */
#define NCLS   460
#define FIN    1024

// ------------------------- scratch (device globals, no allocs) -------------
__device__ float g_xl[(size_t)NNODES * HC];
__device__ float g_xr[(size_t)NNODES * HC];
__device__ int   g_count[NNODES];
__device__ int   g_rowstart[NNODES + 1];
__device__ int   g_cursor[NNODES];
__device__ int   g_csr[ET];                      // stores SRC node per slot
// bf16 hi/lo splits
__device__ __nv_bfloat16 g_xhi[(size_t)NNODES * FIN];
__device__ __nv_bfloat16 g_xlo[(size_t)NNODES * FIN];
__device__ __nv_bfloat16 g_wThi[(size_t)2 * HC * FIN];  // [WlT ; WrT] concat
__device__ __nv_bfloat16 g_wTlo[(size_t)2 * HC * FIN];
__device__ float         g_bcat[2 * HC];                // bl || br
__device__ __nv_bfloat16 g_hmhi[(size_t)NNODES * CH];
__device__ __nv_bfloat16 g_hmlo[(size_t)NNODES * CH];
__device__ __nv_bfloat16 g_wfcThi[(size_t)512 * CH];
__device__ __nv_bfloat16 g_wfcTlo[(size_t)512 * CH];

// ------------------------- split/transpose prep -----------------------------
__global__ void x_split(const float* __restrict__ x)
{
    int i = blockIdx.x * blockDim.x + threadIdx.x;
    if (i >= NNODES * FIN) return;
    float v = x[i];
    __nv_bfloat16 hi = __float2bfloat16_rn(v);
    float lo = v - __bfloat162float(hi);
    g_xhi[i] = hi;
    g_xlo[i] = __float2bfloat16_rn(lo);
}

__global__ void k_bias_cat(const float* __restrict__ bl,
                           const float* __restrict__ br)
{
    int i = blockIdx.x * blockDim.x + threadIdx.x;
    if (i < HC)            g_bcat[i] = bl[i];
    else if (i < 2 * HC)   g_bcat[i] = br[i - HC];
}

// W [K][Ntot] -> T hi/lo [Ntot][K]  (generalized, clamped)
__global__ __launch_bounds__(256) void w_splitT_g(
    const float* __restrict__ W, __nv_bfloat16* __restrict__ Thi,
    __nv_bfloat16* __restrict__ Tlo, int Ntot, int K)
{
    __shared__ float tile[32][33];
    int tx = threadIdx.x & 31;
    int ty = threadIdx.x >> 5;
    int n0 = blockIdx.x * 32;
    int k0 = blockIdx.y * 32;
#pragma unroll
    for (int i = ty; i < 32; i += 8) {
        float v = 0.f;
        if (n0 + tx < Ntot) v = W[(size_t)(k0 + i) * Ntot + n0 + tx];
        tile[i][tx] = v;
    }
    __syncthreads();
#pragma unroll
    for (int i = ty; i < 32; i += 8) {
        if (n0 + i < Ntot) {
            float v = tile[tx][i];
            __nv_bfloat16 hi = __float2bfloat16_rn(v);
            float lo = v - __bfloat162float(hi);
            size_t o = (size_t)(n0 + i) * K + k0 + tx;
            Thi[o] = hi;
            Tlo[o] = __float2bfloat16_rn(lo);
        }
    }
}

// ------------------------- HMMA bf16-split GEMM ------------------------------
#define KC       32
#define NCHUNK   (FIN / KC)        /* 32 */
#define STRIDE   20                /* uint32 per smem row (16 data + 4 pad) */

__device__ __forceinline__ uint32_t smem_u32(const void* p) {
    uint32_t a;
    asm("{ .reg .u64 t; cvta.to.shared.u64 t, %1; cvt.u32.u64 %0, t; }"
        : "=r"(a) : "l"(p));
    return a;
}
__device__ __forceinline__ void cp16(uint32_t saddr, const void* g, int src_sz) {
    asm volatile("cp.async.cg.shared.global [%0], [%1], 16, %2;"
                 :: "r"(saddr), "l"(g), "r"(src_sz));
}
__device__ __forceinline__ void ldm_x4(uint32_t& r0, uint32_t& r1,
                                       uint32_t& r2, uint32_t& r3, uint32_t addr) {
    asm volatile("ldmatrix.sync.aligned.m8n8.x4.shared.b16 {%0,%1,%2,%3}, [%4];"
                 : "=r"(r0), "=r"(r1), "=r"(r2), "=r"(r3) : "r"(addr));
}
__device__ __forceinline__ void mma_bf16(float& c0, float& c1, float& c2, float& c3,
                                         uint32_t a0, uint32_t a1, uint32_t a2,
                                         uint32_t a3, uint32_t b0, uint32_t b1) {
    asm volatile(
        "mma.sync.aligned.m16n8k16.row.col.f32.bf16.bf16.f32 "
        "{%0,%1,%2,%3}, {%4,%5,%6,%7}, {%8,%9}, {%0,%1,%2,%3};"
        : "+f"(c0), "+f"(c1), "+f"(c2), "+f"(c3)
        : "r"(a0), "r"(a1), "r"(a2), "r"(a3), "r"(b0), "r"(b1));
}

// C[M x Nn] = A[M x FIN] @ BT[Nn x FIN]^T + bias[Nn]
// N tile = NTI*32 per CTA. If splitN>0, CTAs with colBase>=splitN write to Cb
// at column (col - splitN); both outputs use row stride ldC.
template<int NTI>
__global__ __launch_bounds__(256) void gemm_mma(
    const __nv_bfloat16* __restrict__ Ahi, const __nv_bfloat16* __restrict__ Alo,
    const __nv_bfloat16* __restrict__ BThi, const __nv_bfloat16* __restrict__ BTlo,
    const float* __restrict__ bias, float* __restrict__ C,
    float* __restrict__ Cb, int splitN,
    int M, int Nn, int ldC)
{
    constexpr int BUFA = 128 * STRIDE;
    constexpr int BUFB = NTI * 32 * STRIDE;
    constexpr int O_AHI = 0;
    constexpr int O_ALO = BUFA;
    constexpr int O_BHI = 2 * BUFA;
    constexpr int O_BLO = 2 * BUFA + BUFB;
    constexpr int STG   = 2 * BUFA + 2 * BUFB;    // u32 per stage

    extern __shared__ uint32_t smem[];
    const uint32_t sbase = smem_u32(smem);
    const int t = threadIdx.x;
    const int w = t >> 5;
    const int lane = t & 31;
    const int gid = lane >> 2;
    const int tg  = lane & 3;
    const int warpM = w & 1;
    const int warpN = w >> 1;
    const int rowBase = blockIdx.y * 128;
    const int colBase = blockIdx.x * (NTI * 32);

    const int a_row = (lane & 7) + ((lane >> 3) & 1) * 8;
    const int a_kh  = (lane >> 4) & 1;
    const int b_row = (lane & 7) + ((lane >> 4) & 1) * 8;
    const int b_kh  = (lane >> 3) & 1;

    auto issue = [&](int c, int s) {
        const int k0 = c * KC;
        const uint32_t base = sbase + s * (STG * 4);
        // A: 128 rows x 4 quarters
#pragma unroll
        for (int i = 0; i < 2; i++) {
            int idx = t + i * 256;
            int row = idx >> 2;
            int q   = idx & 3;
            uint32_t soff = (uint32_t)(row * STRIDE + q * 4) * 4;
            int ar = rowBase + row;
            int ok = (ar < M) ? 16 : 0;
            int arc = (ar < M) ? ar : 0;
            size_t ga = (size_t)arc * FIN + k0 + q * 8;
            cp16(base + O_AHI * 4 + soff, Ahi + ga, ok);
            cp16(base + O_ALO * 4 + soff, Alo + ga, ok);
        }
        // B: NTI*32 rows x 4 quarters
#pragma unroll
        for (int i = 0; i < NTI / 2; i++) {
            int idx = t + i * 256;
            int row = idx >> 2;
            int q   = idx & 3;
            uint32_t soff = (uint32_t)(row * STRIDE + q * 4) * 4;
            int br = colBase + row;
            int okb = (br < Nn) ? 16 : 0;
            int brc = (br < Nn) ? br : 0;
            size_t gb = (size_t)brc * FIN + k0 + q * 8;
            cp16(base + O_BHI * 4 + soff, BThi + gb, okb);
            cp16(base + O_BLO * 4 + soff, BTlo + gb, okb);
        }
        asm volatile("cp.async.commit_group;");
    };

    float acc[4][NTI][4];
#pragma unroll
    for (int mt = 0; mt < 4; mt++)
#pragma unroll
        for (int nt = 0; nt < NTI; nt++)
#pragma unroll
            for (int r = 0; r < 4; r++) acc[mt][nt][r] = 0.f;

    issue(0, 0);

    for (int c = 0; c < NCHUNK; c++) {
        if (c + 1 < NCHUNK) {
            issue(c + 1, (c + 1) & 1);
            asm volatile("cp.async.wait_group 1;");
        } else {
            asm volatile("cp.async.wait_group 0;");
        }
        __syncthreads();

        const uint32_t sb = sbase + (c & 1) * (STG * 4);

#pragma unroll
        for (int ks = 0; ks < 2; ks++) {
            uint32_t ah[4][4], al[4][4];
#pragma unroll
            for (int mt = 0; mt < 4; mt++) {
                uint32_t ra = sb + O_AHI * 4 +
                    (uint32_t)(((warpM * 64 + mt * 16 + a_row) * STRIDE) +
                               ks * 8 + a_kh * 4) * 4;
                ldm_x4(ah[mt][0], ah[mt][1], ah[mt][2], ah[mt][3], ra);
                ldm_x4(al[mt][0], al[mt][1], al[mt][2], al[mt][3],
                       ra + (O_ALO - O_AHI) * 4);
            }
            uint32_t bh[NTI][2], bl[NTI][2];
#pragma unroll
            for (int ntp = 0; ntp < NTI / 2; ntp++) {
                uint32_t rb = sb + O_BHI * 4 +
                    (uint32_t)(((warpN * (NTI * 8) + ntp * 16 + b_row) * STRIDE) +
                               ks * 8 + b_kh * 4) * 4;
                ldm_x4(bh[2 * ntp][0], bh[2 * ntp][1],
                       bh[2 * ntp + 1][0], bh[2 * ntp + 1][1], rb);
                ldm_x4(bl[2 * ntp][0], bl[2 * ntp][1],
                       bl[2 * ntp + 1][0], bl[2 * ntp + 1][1],
                       rb + (O_BLO - O_BHI) * 4);
            }
#pragma unroll
            for (int nt = 0; nt < NTI; nt++) {
#pragma unroll
                for (int mt = 0; mt < 4; mt++) {
                    float* cc = acc[mt][nt];
                    mma_bf16(cc[0], cc[1], cc[2], cc[3],
                             ah[mt][0], ah[mt][1], ah[mt][2], ah[mt][3],
                             bh[nt][0], bh[nt][1]);
                    mma_bf16(cc[0], cc[1], cc[2], cc[3],
                             ah[mt][0], ah[mt][1], ah[mt][2], ah[mt][3],
                             bl[nt][0], bl[nt][1]);
                    mma_bf16(cc[0], cc[1], cc[2], cc[3],
                             al[mt][0], al[mt][1], al[mt][2], al[mt][3],
                             bh[nt][0], bh[nt][1]);
                }
            }
        }
        __syncthreads();
    }

    // epilogue — CTA-level output routing (splitN is tile-aligned)
    float* Cuse = C;
    int coff = 0;
    if (splitN > 0 && colBase >= splitN) { Cuse = Cb; coff = splitN; }

#pragma unroll
    for (int mt = 0; mt < 4; mt++) {
        int r0 = rowBase + warpM * 64 + mt * 16 + gid;
        int r1 = r0 + 8;
#pragma unroll
        for (int nt = 0; nt < NTI; nt++) {
            int cb = colBase + warpN * (NTI * 8) + nt * 8 + tg * 2;
            if (cb >= Nn) continue;
            float b0 = bias[cb], b1 = bias[cb + 1];
            int cc = cb - coff;
            if (r0 < M) {
                float2 o = make_float2(acc[mt][nt][0] + b0, acc[mt][nt][1] + b1);
                *(float2*)(Cuse + (size_t)r0 * ldC + cc) = o;
            }
            if (r1 < M) {
                float2 o = make_float2(acc[mt][nt][2] + b0, acc[mt][nt][3] + b1);
                *(float2*)(Cuse + (size_t)r1 * ldC + cc) = o;
            }
        }
    }
}

// ------------------------- CSR build ---------------------------------------
__global__ void k_zero_counts()
{
    int i = blockIdx.x * blockDim.x + threadIdx.x;
    if (i < NNODES) g_count[i] = 0;
}
__global__ void k_count(const int* __restrict__ ei)
{
    int e = blockIdx.x * blockDim.x + threadIdx.x;
    if (e >= ET) return;
    int dst = (e < NEDGES) ? ei[2 * e + 1] : (e - NEDGES);
    atomicAdd(&g_count[dst], 1);
}
__global__ __launch_bounds__(1024) void k_scan()
{
    __shared__ int sh[1024];
    __shared__ int carry;
    int tid = threadIdx.x;
    if (tid == 0) carry = 0;
    __syncthreads();
    for (int base = 0; base < NNODES; base += 1024) {
        int i = base + tid;
        int v = (i < NNODES) ? g_count[i] : 0;
        sh[tid] = v;
        __syncthreads();
        for (int off = 1; off < 1024; off <<= 1) {
            int t = (tid >= off) ? sh[tid - off] : 0;
            __syncthreads();
            sh[tid] += t;
            __syncthreads();
        }
        int excl = carry + sh[tid] - v;
        if (i < NNODES) { g_rowstart[i] = excl; g_cursor[i] = excl; }
        __syncthreads();
        if (tid == 1023) carry += sh[1023];
        __syncthreads();
    }
    if (tid == 0) g_rowstart[NNODES] = carry;
}
__global__ void k_scatter(const int* __restrict__ ei)
{
    int e = blockIdx.x * blockDim.x + threadIdx.x;
    if (e >= ET) return;
    int src, dst;
    if (e < NEDGES) { src = ei[2 * e]; dst = ei[2 * e + 1]; }
    else            { src = dst = e - NEDGES; }
    int pos = atomicAdd(&g_cursor[dst], 1);
    g_csr[pos] = src;
}

// ------------------------- fused scores + softmax + aggregate ---------------
__global__ __launch_bounds__(128) void node_fused(
    const float* __restrict__ att, const float* __restrict__ bias)
{
    __shared__ float4 satt[HC / 4];      // 12 KB
    __shared__ float  red[4][NH];

    const int node = blockIdx.x;
    const int t = threadIdx.x;
    const int w = t >> 5;
    const int lane = t & 31;

    for (int i = t; i < HC / 4; i += 128)
        satt[i] = ((const float4*)att)[i];

    const int beg = g_rowstart[node];
    const int end = g_rowstart[node + 1];

    float4 xr[NH][2];
    {
        const float4* xrp = (const float4*)(g_xr + (size_t)node * HC);
#pragma unroll
        for (int h = 0; h < NH; h++)
#pragma unroll
            for (int q = 0; q < 2; q++)
                xr[h][q] = xrp[h * 256 + t + 128 * q];
    }
    __syncthreads();

    float m[NH], d[NH];
    float4 acc[NH][2];
#pragma unroll
    for (int h = 0; h < NH; h++) {
        m[h] = -3.0e38f;
        d[h] = 0.f;
#pragma unroll
        for (int q = 0; q < 2; q++) acc[h][q] = make_float4(0.f, 0.f, 0.f, 0.f);
    }

    float4 cur[NH][2];
    if (beg < end) {
        const float4* xlp = (const float4*)(g_xl + (size_t)g_csr[beg] * HC);
#pragma unroll
        for (int h = 0; h < NH; h++)
#pragma unroll
            for (int q = 0; q < 2; q++)
                cur[h][q] = xlp[h * 256 + t + 128 * q];
    }

    for (int p = beg; p < end; p++) {
        float4 nxt[NH][2];
        if (p + 1 < end) {
            const float4* xln = (const float4*)(g_xl + (size_t)g_csr[p + 1] * HC);
#pragma unroll
            for (int h = 0; h < NH; h++)
#pragma unroll
                for (int q = 0; q < 2; q++)
                    nxt[h][q] = xln[h * 256 + t + 128 * q];
        }

        float part[NH];
#pragma unroll
        for (int h = 0; h < NH; h++) {
            part[h] = 0.f;
#pragma unroll
            for (int q = 0; q < 2; q++) {
                float4 v = cur[h][q];
                float4 r = xr[h][q];
                float4 a = satt[h * 256 + t + 128 * q];
                float sx = v.x + r.x; sx = sx > 0.f ? sx : 0.2f * sx;
                float sy = v.y + r.y; sy = sy > 0.f ? sy : 0.2f * sy;
                float sz = v.z + r.z; sz = sz > 0.f ? sz : 0.2f * sz;
                float sw = v.w + r.w; sw = sw > 0.f ? sw : 0.2f * sw;
                part[h] += sx * a.x + sy * a.y + sz * a.z + sw * a.w;
            }
        }
#pragma unroll
        for (int off = 16; off; off >>= 1)
#pragma unroll
            for (int h = 0; h < NH; h++)
                part[h] += __shfl_xor_sync(0xFFFFFFFFu, part[h], off);
        if (lane == 0)
#pragma unroll
            for (int h = 0; h < NH; h++) red[w][h] = part[h];
        __syncthreads();

        float s[NH];
#pragma unroll
        for (int h = 0; h < NH; h++)
            s[h] = red[0][h] + red[1][h] + red[2][h] + red[3][h];
        __syncthreads();

#pragma unroll
        for (int h = 0; h < NH; h++) {
            float e;
            if (s[h] > m[h]) {
                float sc = __expf(m[h] - s[h]);
                d[h] *= sc;
#pragma unroll
                for (int q = 0; q < 2; q++) {
                    acc[h][q].x *= sc; acc[h][q].y *= sc;
                    acc[h][q].z *= sc; acc[h][q].w *= sc;
                }
                m[h] = s[h];
                e = 1.f;
            } else {
                e = __expf(s[h] - m[h]);
            }
            d[h] += e;
#pragma unroll
            for (int q = 0; q < 2; q++) {
                acc[h][q].x += e * cur[h][q].x;
                acc[h][q].y += e * cur[h][q].y;
                acc[h][q].z += e * cur[h][q].z;
                acc[h][q].w += e * cur[h][q].w;
            }
        }

        if (p + 1 < end) {
#pragma unroll
            for (int h = 0; h < NH; h++)
#pragma unroll
                for (int q = 0; q < 2; q++)
                    cur[h][q] = nxt[h][q];
        }
    }

    float invd[NH];
#pragma unroll
    for (int h = 0; h < NH; h++) invd[h] = 1.f / (d[h] + 1e-16f);

    const float inv3 = 1.0f / 3.0f;
#pragma unroll
    for (int q = 0; q < 2; q++) {
        int f = t + 128 * q;
        float o[4];
        o[0] = (acc[0][q].x * invd[0] + acc[1][q].x * invd[1] + acc[2][q].x * invd[2]) * inv3 + bias[4 * f + 0];
        o[1] = (acc[0][q].y * invd[0] + acc[1][q].y * invd[1] + acc[2][q].y * invd[2]) * inv3 + bias[4 * f + 1];
        o[2] = (acc[0][q].z * invd[0] + acc[1][q].z * invd[1] + acc[2][q].z * invd[2]) * inv3 + bias[4 * f + 2];
        o[3] = (acc[0][q].w * invd[0] + acc[1][q].w * invd[1] + acc[2][q].w * invd[2]) * inv3 + bias[4 * f + 3];
        __nv_bfloat16 hi[4], lo[4];
#pragma unroll
        for (int j = 0; j < 4; j++) {
            hi[j] = __float2bfloat16_rn(o[j]);
            lo[j] = __float2bfloat16_rn(o[j] - __bfloat162float(hi[j]));
        }
        size_t idx = (size_t)node * CH + 4 * f;
        *(uint2*)(g_hmhi + idx) = *(uint2*)hi;
        *(uint2*)(g_hmlo + idx) = *(uint2*)lo;
    }
}

// ------------------------- pass-through copy --------------------------------
__global__ void k_copy4(const float4* __restrict__ src, float4* __restrict__ dst,
                        int n4)
{
    int i = blockIdx.x * blockDim.x + threadIdx.x;
    if (i < n4) dst[i] = src[i];
}

// ------------------------- launch ------------------------------------------
extern "C" void kernel_launch(void* const* d_in, const int* in_sizes, int n_in,
                              void* d_out, int out_size)
{
    const float* x    = (const float*)d_in[0];
    const int*   ei   = (const int*)d_in[1];
    const float* Wl   = (const float*)d_in[2];
    const float* bl   = (const float*)d_in[3];
    const float* Wr   = (const float*)d_in[4];
    const float* br   = (const float*)d_in[5];
    const float* att  = (const float*)d_in[6];
    const float* bias = (const float*)d_in[7];
    const float* Wfc  = (const float*)d_in[8];
    const float* bfc  = (const float*)d_in[9];
    const float* exps   = (const float*)d_in[10];
    const float* exps_c = (const float*)d_in[11];
    float* out = (float*)d_out;

    constexpr int SMEM4 = 2 * (2 * 128 * STRIDE + 2 * 128 * STRIDE) * 4; // 81920
    constexpr int SMEM2 = 2 * (2 * 128 * STRIDE + 2 * 64 * STRIDE) * 4;  // 61440
    cudaFuncSetAttribute(gemm_mma<4>, cudaFuncAttributeMaxDynamicSharedMemorySize,
                         SMEM4);
    cudaFuncSetAttribute(gemm_mma<2>, cudaFuncAttributeMaxDynamicSharedMemorySize,
                         SMEM2);

    // device addresses (NOT host shadow symbols — GB300 ATS trap)
    float *pxl, *pxr, *pbcat;
    __nv_bfloat16 *pxhi, *pxlo, *pwThi, *pwTlo;
    __nv_bfloat16 *phmhi, *phmlo, *pfcThi, *pfcTlo;
    cudaGetSymbolAddress((void**)&pxl,    g_xl);
    cudaGetSymbolAddress((void**)&pxr,    g_xr);
    cudaGetSymbolAddress((void**)&pbcat,  g_bcat);
    cudaGetSymbolAddress((void**)&pxhi,   g_xhi);
    cudaGetSymbolAddress((void**)&pxlo,   g_xlo);
    cudaGetSymbolAddress((void**)&pwThi,  g_wThi);
    cudaGetSymbolAddress((void**)&pwTlo,  g_wTlo);
    cudaGetSymbolAddress((void**)&phmhi,  g_hmhi);
    cudaGetSymbolAddress((void**)&phmlo,  g_hmlo);
    cudaGetSymbolAddress((void**)&pfcThi, g_wfcThi);
    cudaGetSymbolAddress((void**)&pfcTlo, g_wfcTlo);

    // bf16 hi/lo splits of x and W^T (WlT into rows [0,HC), WrT into [HC,2HC))
    x_split<<<(NNODES * FIN + 255) / 256, 256>>>(x);
    {
        dim3 grid(HC / 32, FIN / 32);
        w_splitT_g<<<grid, 256>>>(Wl, pwThi, pwTlo, HC, FIN);
        w_splitT_g<<<grid, 256>>>(Wr, pwThi + (size_t)HC * FIN,
                                      pwTlo + (size_t)HC * FIN, HC, FIN);
    }
    {
        dim3 grid((NCLS + 31) / 32, CH / 32);
        w_splitT_g<<<grid, 256>>>(Wfc, pfcThi, pfcTlo, NCLS, CH);
    }
    k_bias_cat<<<(2 * HC + 255) / 256, 256>>>(bl, br);

    // BOTH projections in ONE launch: N = 2*HC, columns >= HC go to g_xr
    {
        dim3 grid((2 * HC) / 128, (NNODES + 127) / 128);
        gemm_mma<4><<<grid, 256, SMEM4>>>(pxhi, pxlo, pwThi, pwTlo,
                                          pbcat, pxl, pxr, HC,
                                          NNODES, 2 * HC, HC);
    }

    // CSR by destination
    k_zero_counts<<<(NNODES + 255) / 256, 256>>>();
    k_count<<<(ET + 255) / 256, 256>>>(ei);
    k_scan<<<1, 1024>>>();
    k_scatter<<<(ET + 255) / 256, 256>>>(ei);

    // fused scores + online softmax + aggregation + head mean + bias
    node_fused<<<NNODES, 128>>>(att, bias);

    // fc readout: narrow N tile (64) to cut the tail
    {
        dim3 grid((NCLS + 63) / 64, (NNODES + 127) / 128);
        gemm_mma<2><<<grid, 256, SMEM2>>>(phmhi, phmlo, pfcThi, pfcTlo,
                                          bfc, out, nullptr, 0,
                                          NNODES, NCLS, NCLS);
    }

    // pass-through outputs
    size_t hElems = (size_t)NNODES * NCLS;
    int n4a = in_sizes[10] / 4;
    int n4b = in_sizes[11] / 4;
    k_copy4<<<(n4a + 255) / 256, 256>>>((const float4*)exps,
                                        (float4*)(out + hElems), n4a);
    k_copy4<<<(n4b + 255) / 256, 256>>>((const float4*)exps_c,
                                        (float4*)(out + hElems + in_sizes[10]), n4b);
}

// round 13
// speedup vs baseline: 1.1053x; 1.0026x over previous
#include <cuda_runtime.h>
#include <cuda_bf16.h>
#include <math.h>
#include <stdint.h>

#define NNODES 10000
#define NEDGES 100000
#define NH     3
#define CH     1024
#define HC     3072          /* NH*CH */
#define ET     110000        /* NEDGES + NNODES self loops */
#define NCLS   460
#define FIN    1024

// ------------------------- scratch (device globals, no allocs) -------------
__device__ float g_xl[(size_t)NNODES * HC];
__device__ float g_xr[(size_t)NNODES * HC];
__device__ int   g_count[NNODES];
__device__ int   g_rowstart[NNODES + 1];
__device__ int   g_cursor[NNODES];
__device__ int   g_csr[ET];                      // stores SRC node per slot
// bf16 hi/lo splits
__device__ __nv_bfloat16 g_xhi[(size_t)NNODES * FIN];
__device__ __nv_bfloat16 g_xlo[(size_t)NNODES * FIN];
__device__ __nv_bfloat16 g_wThi[(size_t)2 * HC * FIN];  // [WlT ; WrT] concat
__device__ __nv_bfloat16 g_wTlo[(size_t)2 * HC * FIN];
__device__ float         g_bcat[2 * HC];                // bl || br
__device__ __nv_bfloat16 g_hmhi[(size_t)NNODES * CH];
__device__ __nv_bfloat16 g_hmlo[(size_t)NNODES * CH];
__device__ __nv_bfloat16 g_wfcThi[(size_t)512 * CH];
__device__ __nv_bfloat16 g_wfcTlo[(size_t)512 * CH];

// ------------------------- split/transpose prep -----------------------------
__global__ void x_split(const float* __restrict__ x)
{
    int i = blockIdx.x * blockDim.x + threadIdx.x;
    if (i >= NNODES * FIN) return;
    float v = x[i];
    __nv_bfloat16 hi = __float2bfloat16_rn(v);
    float lo = v - __bfloat162float(hi);
    g_xhi[i] = hi;
    g_xlo[i] = __float2bfloat16_rn(lo);
}

__global__ void k_bias_cat(const float* __restrict__ bl,
                           const float* __restrict__ br)
{
    int i = blockIdx.x * blockDim.x + threadIdx.x;
    if (i < HC)            g_bcat[i] = bl[i];
    else if (i < 2 * HC)   g_bcat[i] = br[i - HC];
}

// W [K][Ntot] -> T hi/lo [Ntot][K]  (generalized, clamped)
__global__ __launch_bounds__(256) void w_splitT_g(
    const float* __restrict__ W, __nv_bfloat16* __restrict__ Thi,
    __nv_bfloat16* __restrict__ Tlo, int Ntot, int K)
{
    __shared__ float tile[32][33];
    int tx = threadIdx.x & 31;
    int ty = threadIdx.x >> 5;
    int n0 = blockIdx.x * 32;
    int k0 = blockIdx.y * 32;
#pragma unroll
    for (int i = ty; i < 32; i += 8) {
        float v = 0.f;
        if (n0 + tx < Ntot) v = W[(size_t)(k0 + i) * Ntot + n0 + tx];
        tile[i][tx] = v;
    }
    __syncthreads();
#pragma unroll
    for (int i = ty; i < 32; i += 8) {
        if (n0 + i < Ntot) {
            float v = tile[tx][i];
            __nv_bfloat16 hi = __float2bfloat16_rn(v);
            float lo = v - __bfloat162float(hi);
            size_t o = (size_t)(n0 + i) * K + k0 + tx;
            Thi[o] = hi;
            Tlo[o] = __float2bfloat16_rn(lo);
        }
    }
}

// ------------------------- HMMA bf16-split GEMM ------------------------------
#define KC       32
#define NCHUNK   (FIN / KC)        /* 32 */
#define STRIDE   20                /* uint32 per smem row (16 data + 4 pad) */

__device__ __forceinline__ uint32_t smem_u32(const void* p) {
    uint32_t a;
    asm("{ .reg .u64 t; cvta.to.shared.u64 t, %1; cvt.u32.u64 %0, t; }"
        : "=r"(a) : "l"(p));
    return a;
}
__device__ __forceinline__ void cp16(uint32_t saddr, const void* g, int src_sz) {
    asm volatile("cp.async.cg.shared.global [%0], [%1], 16, %2;"
                 :: "r"(saddr), "l"(g), "r"(src_sz));
}
__device__ __forceinline__ void ldm_x4(uint32_t& r0, uint32_t& r1,
                                       uint32_t& r2, uint32_t& r3, uint32_t addr) {
    asm volatile("ldmatrix.sync.aligned.m8n8.x4.shared.b16 {%0,%1,%2,%3}, [%4];"
                 : "=r"(r0), "=r"(r1), "=r"(r2), "=r"(r3) : "r"(addr));
}
__device__ __forceinline__ void mma_bf16(float& c0, float& c1, float& c2, float& c3,
                                         uint32_t a0, uint32_t a1, uint32_t a2,
                                         uint32_t a3, uint32_t b0, uint32_t b1) {
    asm volatile(
        "mma.sync.aligned.m16n8k16.row.col.f32.bf16.bf16.f32 "
        "{%0,%1,%2,%3}, {%4,%5,%6,%7}, {%8,%9}, {%0,%1,%2,%3};"
        : "+f"(c0), "+f"(c1), "+f"(c2), "+f"(c3)
        : "r"(a0), "r"(a1), "r"(a2), "r"(a3), "r"(b0), "r"(b1));
}

// C[M x Nn] = A[M x FIN] @ BT[Nn x FIN]^T + bias[Nn]
// N tile = NTI*32 per CTA. If splitN>0, CTAs with colBase>=splitN write to Cb
// at column (col - splitN); both outputs use row stride ldC.
template<int NTI>
__global__ __launch_bounds__(256) void gemm_mma(
    const __nv_bfloat16* __restrict__ Ahi, const __nv_bfloat16* __restrict__ Alo,
    const __nv_bfloat16* __restrict__ BThi, const __nv_bfloat16* __restrict__ BTlo,
    const float* __restrict__ bias, float* __restrict__ C,
    float* __restrict__ Cb, int splitN,
    int M, int Nn, int ldC)
{
    constexpr int BUFA = 128 * STRIDE;
    constexpr int BUFB = NTI * 32 * STRIDE;
    constexpr int O_AHI = 0;
    constexpr int O_ALO = BUFA;
    constexpr int O_BHI = 2 * BUFA;
    constexpr int O_BLO = 2 * BUFA + BUFB;
    constexpr int STG   = 2 * BUFA + 2 * BUFB;    // u32 per stage

    extern __shared__ uint32_t smem[];
    const uint32_t sbase = smem_u32(smem);
    const int t = threadIdx.x;
    const int w = t >> 5;
    const int lane = t & 31;
    const int gid = lane >> 2;
    const int tg  = lane & 3;
    const int warpM = w & 1;
    const int warpN = w >> 1;
    const int rowBase = blockIdx.y * 128;
    const int colBase = blockIdx.x * (NTI * 32);

    const int a_row = (lane & 7) + ((lane >> 3) & 1) * 8;
    const int a_kh  = (lane >> 4) & 1;
    const int b_row = (lane & 7) + ((lane >> 4) & 1) * 8;
    const int b_kh  = (lane >> 3) & 1;

    auto issue = [&](int c, int s) {
        const int k0 = c * KC;
        const uint32_t base = sbase + s * (STG * 4);
#pragma unroll
        for (int i = 0; i < 2; i++) {
            int idx = t + i * 256;
            int row = idx >> 2;
            int q   = idx & 3;
            uint32_t soff = (uint32_t)(row * STRIDE + q * 4) * 4;
            int ar = rowBase + row;
            int ok = (ar < M) ? 16 : 0;
            int arc = (ar < M) ? ar : 0;
            size_t ga = (size_t)arc * FIN + k0 + q * 8;
            cp16(base + O_AHI * 4 + soff, Ahi + ga, ok);
            cp16(base + O_ALO * 4 + soff, Alo + ga, ok);
        }
#pragma unroll
        for (int i = 0; i < NTI / 2; i++) {
            int idx = t + i * 256;
            int row = idx >> 2;
            int q   = idx & 3;
            uint32_t soff = (uint32_t)(row * STRIDE + q * 4) * 4;
            int br = colBase + row;
            int okb = (br < Nn) ? 16 : 0;
            int brc = (br < Nn) ? br : 0;
            size_t gb = (size_t)brc * FIN + k0 + q * 8;
            cp16(base + O_BHI * 4 + soff, BThi + gb, okb);
            cp16(base + O_BLO * 4 + soff, BTlo + gb, okb);
        }
        asm volatile("cp.async.commit_group;");
    };

    float acc[4][NTI][4];
#pragma unroll
    for (int mt = 0; mt < 4; mt++)
#pragma unroll
        for (int nt = 0; nt < NTI; nt++)
#pragma unroll
            for (int r = 0; r < 4; r++) acc[mt][nt][r] = 0.f;

    issue(0, 0);

    for (int c = 0; c < NCHUNK; c++) {
        if (c + 1 < NCHUNK) {
            issue(c + 1, (c + 1) & 1);
            asm volatile("cp.async.wait_group 1;");
        } else {
            asm volatile("cp.async.wait_group 0;");
        }
        __syncthreads();

        const uint32_t sb = sbase + (c & 1) * (STG * 4);

#pragma unroll
        for (int ks = 0; ks < 2; ks++) {
            uint32_t ah[4][4], al[4][4];
#pragma unroll
            for (int mt = 0; mt < 4; mt++) {
                uint32_t ra = sb + O_AHI * 4 +
                    (uint32_t)(((warpM * 64 + mt * 16 + a_row) * STRIDE) +
                               ks * 8 + a_kh * 4) * 4;
                ldm_x4(ah[mt][0], ah[mt][1], ah[mt][2], ah[mt][3], ra);
                ldm_x4(al[mt][0], al[mt][1], al[mt][2], al[mt][3],
                       ra + (O_ALO - O_AHI) * 4);
            }
            uint32_t bh[NTI][2], bl[NTI][2];
#pragma unroll
            for (int ntp = 0; ntp < NTI / 2; ntp++) {
                uint32_t rb = sb + O_BHI * 4 +
                    (uint32_t)(((warpN * (NTI * 8) + ntp * 16 + b_row) * STRIDE) +
                               ks * 8 + b_kh * 4) * 4;
                ldm_x4(bh[2 * ntp][0], bh[2 * ntp][1],
                       bh[2 * ntp + 1][0], bh[2 * ntp + 1][1], rb);
                ldm_x4(bl[2 * ntp][0], bl[2 * ntp][1],
                       bl[2 * ntp + 1][0], bl[2 * ntp + 1][1],
                       rb + (O_BLO - O_BHI) * 4);
            }
            // term-outermost ordering: 16 consecutive HMMAs hit DIFFERENT
            // accumulators (no RAW chains back-to-back); per-acc order is
            // still hh, hl, lh — numerics identical to previous rounds.
#pragma unroll
            for (int term = 0; term < 3; term++) {
#pragma unroll
                for (int nt = 0; nt < NTI; nt++) {
#pragma unroll
                    for (int mt = 0; mt < 4; mt++) {
                        float* cc = acc[mt][nt];
                        const uint32_t* aa = (term == 2) ? al[mt] : ah[mt];
                        const uint32_t* bb = (term == 1) ? bl[nt] : bh[nt];
                        mma_bf16(cc[0], cc[1], cc[2], cc[3],
                                 aa[0], aa[1], aa[2], aa[3], bb[0], bb[1]);
                    }
                }
            }
        }
        __syncthreads();
    }

    // epilogue — CTA-level output routing (splitN is tile-aligned)
    float* Cuse = C;
    int coff = 0;
    if (splitN > 0 && colBase >= splitN) { Cuse = Cb; coff = splitN; }

#pragma unroll
    for (int mt = 0; mt < 4; mt++) {
        int r0 = rowBase + warpM * 64 + mt * 16 + gid;
        int r1 = r0 + 8;
#pragma unroll
        for (int nt = 0; nt < NTI; nt++) {
            int cb = colBase + warpN * (NTI * 8) + nt * 8 + tg * 2;
            if (cb >= Nn) continue;
            float b0 = bias[cb], b1 = bias[cb + 1];
            int cc = cb - coff;
            if (r0 < M) {
                float2 o = make_float2(acc[mt][nt][0] + b0, acc[mt][nt][1] + b1);
                *(float2*)(Cuse + (size_t)r0 * ldC + cc) = o;
            }
            if (r1 < M) {
                float2 o = make_float2(acc[mt][nt][2] + b0, acc[mt][nt][3] + b1);
                *(float2*)(Cuse + (size_t)r1 * ldC + cc) = o;
            }
        }
    }
}

// ------------------------- CSR build ---------------------------------------
__global__ void k_zero_counts()
{
    int i = blockIdx.x * blockDim.x + threadIdx.x;
    if (i < NNODES) g_count[i] = 0;
}
__global__ void k_count(const int* __restrict__ ei)
{
    int e = blockIdx.x * blockDim.x + threadIdx.x;
    if (e >= ET) return;
    int dst = (e < NEDGES) ? ei[2 * e + 1] : (e - NEDGES);
    atomicAdd(&g_count[dst], 1);
}
__global__ __launch_bounds__(1024) void k_scan()
{
    __shared__ int sh[1024];
    __shared__ int carry;
    int tid = threadIdx.x;
    if (tid == 0) carry = 0;
    __syncthreads();
    for (int base = 0; base < NNODES; base += 1024) {
        int i = base + tid;
        int v = (i < NNODES) ? g_count[i] : 0;
        sh[tid] = v;
        __syncthreads();
        for (int off = 1; off < 1024; off <<= 1) {
            int t = (tid >= off) ? sh[tid - off] : 0;
            __syncthreads();
            sh[tid] += t;
            __syncthreads();
        }
        int excl = carry + sh[tid] - v;
        if (i < NNODES) { g_rowstart[i] = excl; g_cursor[i] = excl; }
        __syncthreads();
        if (tid == 1023) carry += sh[1023];
        __syncthreads();
    }
    if (tid == 0) g_rowstart[NNODES] = carry;
}
__global__ void k_scatter(const int* __restrict__ ei)
{
    int e = blockIdx.x * blockDim.x + threadIdx.x;
    if (e >= ET) return;
    int src, dst;
    if (e < NEDGES) { src = ei[2 * e]; dst = ei[2 * e + 1]; }
    else            { src = dst = e - NEDGES; }
    int pos = atomicAdd(&g_cursor[dst], 1);
    g_csr[pos] = src;
}

// ------------------------- fused scores + softmax + aggregate ---------------
__global__ __launch_bounds__(128) void node_fused(
    const float* __restrict__ att, const float* __restrict__ bias)
{
    __shared__ float4 satt[HC / 4];      // 12 KB
    __shared__ float  red[4][NH];

    const int node = blockIdx.x;
    const int t = threadIdx.x;
    const int w = t >> 5;
    const int lane = t & 31;

    for (int i = t; i < HC / 4; i += 128)
        satt[i] = ((const float4*)att)[i];

    const int beg = g_rowstart[node];
    const int end = g_rowstart[node + 1];

    float4 xr[NH][2];
    {
        const float4* xrp = (const float4*)(g_xr + (size_t)node * HC);
#pragma unroll
        for (int h = 0; h < NH; h++)
#pragma unroll
            for (int q = 0; q < 2; q++)
                xr[h][q] = xrp[h * 256 + t + 128 * q];
    }
    __syncthreads();

    float m[NH], d[NH];
    float4 acc[NH][2];
#pragma unroll
    for (int h = 0; h < NH; h++) {
        m[h] = -3.0e38f;
        d[h] = 0.f;
#pragma unroll
        for (int q = 0; q < 2; q++) acc[h][q] = make_float4(0.f, 0.f, 0.f, 0.f);
    }

    float4 cur[NH][2];
    if (beg < end) {
        const float4* xlp = (const float4*)(g_xl + (size_t)g_csr[beg] * HC);
#pragma unroll
        for (int h = 0; h < NH; h++)
#pragma unroll
            for (int q = 0; q < 2; q++)
                cur[h][q] = xlp[h * 256 + t + 128 * q];
    }

    for (int p = beg; p < end; p++) {
        float4 nxt[NH][2];
        if (p + 1 < end) {
            const float4* xln = (const float4*)(g_xl + (size_t)g_csr[p + 1] * HC);
#pragma unroll
            for (int h = 0; h < NH; h++)
#pragma unroll
                for (int q = 0; q < 2; q++)
                    nxt[h][q] = xln[h * 256 + t + 128 * q];
        }

        float part[NH];
#pragma unroll
        for (int h = 0; h < NH; h++) {
            part[h] = 0.f;
#pragma unroll
            for (int q = 0; q < 2; q++) {
                float4 v = cur[h][q];
                float4 r = xr[h][q];
                float4 a = satt[h * 256 + t + 128 * q];
                float sx = v.x + r.x; sx = sx > 0.f ? sx : 0.2f * sx;
                float sy = v.y + r.y; sy = sy > 0.f ? sy : 0.2f * sy;
                float sz = v.z + r.z; sz = sz > 0.f ? sz : 0.2f * sz;
                float sw = v.w + r.w; sw = sw > 0.f ? sw : 0.2f * sw;
                part[h] += sx * a.x + sy * a.y + sz * a.z + sw * a.w;
            }
        }
#pragma unroll
        for (int off = 16; off; off >>= 1)
#pragma unroll
            for (int h = 0; h < NH; h++)
                part[h] += __shfl_xor_sync(0xFFFFFFFFu, part[h], off);
        if (lane == 0)
#pragma unroll
            for (int h = 0; h < NH; h++) red[w][h] = part[h];
        __syncthreads();

        float s[NH];
#pragma unroll
        for (int h = 0; h < NH; h++)
            s[h] = red[0][h] + red[1][h] + red[2][h] + red[3][h];
        __syncthreads();

#pragma unroll
        for (int h = 0; h < NH; h++) {
            float e;
            if (s[h] > m[h]) {
                float sc = __expf(m[h] - s[h]);
                d[h] *= sc;
#pragma unroll
                for (int q = 0; q < 2; q++) {
                    acc[h][q].x *= sc; acc[h][q].y *= sc;
                    acc[h][q].z *= sc; acc[h][q].w *= sc;
                }
                m[h] = s[h];
                e = 1.f;
            } else {
                e = __expf(s[h] - m[h]);
            }
            d[h] += e;
#pragma unroll
            for (int q = 0; q < 2; q++) {
                acc[h][q].x += e * cur[h][q].x;
                acc[h][q].y += e * cur[h][q].y;
                acc[h][q].z += e * cur[h][q].z;
                acc[h][q].w += e * cur[h][q].w;
            }
        }

        if (p + 1 < end) {
#pragma unroll
            for (int h = 0; h < NH; h++)
#pragma unroll
                for (int q = 0; q < 2; q++)
                    cur[h][q] = nxt[h][q];
        }
    }

    float invd[NH];
#pragma unroll
    for (int h = 0; h < NH; h++) invd[h] = 1.f / (d[h] + 1e-16f);

    const float inv3 = 1.0f / 3.0f;
#pragma unroll
    for (int q = 0; q < 2; q++) {
        int f = t + 128 * q;
        float o[4];
        o[0] = (acc[0][q].x * invd[0] + acc[1][q].x * invd[1] + acc[2][q].x * invd[2]) * inv3 + bias[4 * f + 0];
        o[1] = (acc[0][q].y * invd[0] + acc[1][q].y * invd[1] + acc[2][q].y * invd[2]) * inv3 + bias[4 * f + 1];
        o[2] = (acc[0][q].z * invd[0] + acc[1][q].z * invd[1] + acc[2][q].z * invd[2]) * inv3 + bias[4 * f + 2];
        o[3] = (acc[0][q].w * invd[0] + acc[1][q].w * invd[1] + acc[2][q].w * invd[2]) * inv3 + bias[4 * f + 3];
        __nv_bfloat16 hi[4], lo[4];
#pragma unroll
        for (int j = 0; j < 4; j++) {
            hi[j] = __float2bfloat16_rn(o[j]);
            lo[j] = __float2bfloat16_rn(o[j] - __bfloat162float(hi[j]));
        }
        size_t idx = (size_t)node * CH + 4 * f;
        *(uint2*)(g_hmhi + idx) = *(uint2*)hi;
        *(uint2*)(g_hmlo + idx) = *(uint2*)lo;
    }
}

// ------------------------- pass-through copy --------------------------------
__global__ void k_copy4(const float4* __restrict__ src, float4* __restrict__ dst,
                        int n4)
{
    int i = blockIdx.x * blockDim.x + threadIdx.x;
    if (i < n4) dst[i] = src[i];
}

// ------------------------- launch ------------------------------------------
extern "C" void kernel_launch(void* const* d_in, const int* in_sizes, int n_in,
                              void* d_out, int out_size)
{
    const float* x    = (const float*)d_in[0];
    const int*   ei   = (const int*)d_in[1];
    const float* Wl   = (const float*)d_in[2];
    const float* bl   = (const float*)d_in[3];
    const float* Wr   = (const float*)d_in[4];
    const float* br   = (const float*)d_in[5];
    const float* att  = (const float*)d_in[6];
    const float* bias = (const float*)d_in[7];
    const float* Wfc  = (const float*)d_in[8];
    const float* bfc  = (const float*)d_in[9];
    const float* exps   = (const float*)d_in[10];
    const float* exps_c = (const float*)d_in[11];
    float* out = (float*)d_out;

    constexpr int SMEM4 = 2 * (2 * 128 * STRIDE + 2 * 128 * STRIDE) * 4; // 81920
    constexpr int SMEM2 = 2 * (2 * 128 * STRIDE + 2 * 64 * STRIDE) * 4;  // 61440
    cudaFuncSetAttribute(gemm_mma<4>, cudaFuncAttributeMaxDynamicSharedMemorySize,
                         SMEM4);
    cudaFuncSetAttribute(gemm_mma<2>, cudaFuncAttributeMaxDynamicSharedMemorySize,
                         SMEM2);

    // device addresses (NOT host shadow symbols — GB300 ATS trap)
    float *pxl, *pxr, *pbcat;
    __nv_bfloat16 *pxhi, *pxlo, *pwThi, *pwTlo;
    __nv_bfloat16 *phmhi, *phmlo, *pfcThi, *pfcTlo;
    cudaGetSymbolAddress((void**)&pxl,    g_xl);
    cudaGetSymbolAddress((void**)&pxr,    g_xr);
    cudaGetSymbolAddress((void**)&pbcat,  g_bcat);
    cudaGetSymbolAddress((void**)&pxhi,   g_xhi);
    cudaGetSymbolAddress((void**)&pxlo,   g_xlo);
    cudaGetSymbolAddress((void**)&pwThi,  g_wThi);
    cudaGetSymbolAddress((void**)&pwTlo,  g_wTlo);
    cudaGetSymbolAddress((void**)&phmhi,  g_hmhi);
    cudaGetSymbolAddress((void**)&phmlo,  g_hmlo);
    cudaGetSymbolAddress((void**)&pfcThi, g_wfcThi);
    cudaGetSymbolAddress((void**)&pfcTlo, g_wfcTlo);

    // bf16 hi/lo splits of x and W^T (WlT into rows [0,HC), WrT into [HC,2HC))
    x_split<<<(NNODES * FIN + 255) / 256, 256>>>(x);
    {
        dim3 grid(HC / 32, FIN / 32);
        w_splitT_g<<<grid, 256>>>(Wl, pwThi, pwTlo, HC, FIN);
        w_splitT_g<<<grid, 256>>>(Wr, pwThi + (size_t)HC * FIN,
                                      pwTlo + (size_t)HC * FIN, HC, FIN);
    }
    {
        dim3 grid((NCLS + 31) / 32, CH / 32);
        w_splitT_g<<<grid, 256>>>(Wfc, pfcThi, pfcTlo, NCLS, CH);
    }
    k_bias_cat<<<(2 * HC + 255) / 256, 256>>>(bl, br);

    // BOTH projections in ONE launch: N = 2*HC, columns >= HC go to g_xr
    {
        dim3 grid((2 * HC) / 128, (NNODES + 127) / 128);
        gemm_mma<4><<<grid, 256, SMEM4>>>(pxhi, pxlo, pwThi, pwTlo,
                                          pbcat, pxl, pxr, HC,
                                          NNODES, 2 * HC, HC);
    }

    // CSR by destination
    k_zero_counts<<<(NNODES + 255) / 256, 256>>>();
    k_count<<<(ET + 255) / 256, 256>>>(ei);
    k_scan<<<1, 1024>>>();
    k_scatter<<<(ET + 255) / 256, 256>>>(ei);

    // fused scores + online softmax + aggregation + head mean + bias
    node_fused<<<NNODES, 128>>>(att, bias);

    // fc readout: narrow N tile (64) to cut the tail
    {
        dim3 grid((NCLS + 63) / 64, (NNODES + 127) / 128);
        gemm_mma<2><<<grid, 256, SMEM2>>>(phmhi, phmlo, pfcThi, pfcTlo,
                                          bfc, out, nullptr, 0,
                                          NNODES, NCLS, NCLS);
    }

    // pass-through outputs
    size_t hElems = (size_t)NNODES * NCLS;
    int n4a = in_sizes[10] / 4;
    int n4b = in_sizes[11] / 4;
    k_copy4<<<(n4a + 255) / 256, 256>>>((const float4*)exps,
                                        (float4*)(out + hElems), n4a);
    k_copy4<<<(n4b + 255) / 256, 256>>>((const float4*)exps_c,
                                        (float4*)(out + hElems + in_sizes[10]), n4b);
}

// round 14
// speedup vs baseline: 1.1066x; 1.0012x over previous
#include <cuda_runtime.h>
#include <cuda_bf16.h>
#include <math.h>
#include <stdint.h>

#define NNODES 10000
#define NEDGES 100000
#define NH     3
#define CH     1024
#define HC     3072          /* NH*CH */
#define ET     110000        /* NEDGES + NNODES self loops */
#define NCLS   460
#define FIN    1024

// ------------------------- scratch (device globals, no allocs) -------------
__device__ float g_xl[(size_t)NNODES * HC];
__device__ float g_xr[(size_t)NNODES * HC];
__device__ int   g_count[NNODES];
__device__ int   g_rowstart[NNODES + 1];
__device__ int   g_cursor[NNODES];
__device__ int   g_csr[ET];                      // stores SRC node per slot
// bf16 hi/lo splits
__device__ __nv_bfloat16 g_xhi[(size_t)NNODES * FIN];
__device__ __nv_bfloat16 g_xlo[(size_t)NNODES * FIN];
__device__ __nv_bfloat16 g_wThi[(size_t)2 * HC * FIN];  // [WlT ; WrT] concat
__device__ __nv_bfloat16 g_wTlo[(size_t)2 * HC * FIN];
__device__ float         g_bcat[2 * HC];                // bl || br
__device__ __nv_bfloat16 g_hmhi[(size_t)NNODES * CH];
__device__ __nv_bfloat16 g_hmlo[(size_t)NNODES * CH];
__device__ __nv_bfloat16 g_wfcThi[(size_t)512 * CH];
__device__ __nv_bfloat16 g_wfcTlo[(size_t)512 * CH];

// ------------------------- split/transpose prep -----------------------------
// x split + bias concat fused (keeps gemm<4> at launch slot #4 for profiling)
__global__ void x_split(const float* __restrict__ x,
                        const float* __restrict__ bl,
                        const float* __restrict__ br)
{
    int i = blockIdx.x * blockDim.x + threadIdx.x;
    if (i < 2 * HC)
        g_bcat[i] = (i < HC) ? bl[i] : br[i - HC];
    if (i >= NNODES * FIN) return;
    float v = x[i];
    __nv_bfloat16 hi = __float2bfloat16_rn(v);
    float lo = v - __bfloat162float(hi);
    g_xhi[i] = hi;
    g_xlo[i] = __float2bfloat16_rn(lo);
}

// W [K][Ntot] -> T hi/lo [Ntot][K]  (generalized, clamped)
__global__ __launch_bounds__(256) void w_splitT_g(
    const float* __restrict__ W, __nv_bfloat16* __restrict__ Thi,
    __nv_bfloat16* __restrict__ Tlo, int Ntot, int K)
{
    __shared__ float tile[32][33];
    int tx = threadIdx.x & 31;
    int ty = threadIdx.x >> 5;
    int n0 = blockIdx.x * 32;
    int k0 = blockIdx.y * 32;
#pragma unroll
    for (int i = ty; i < 32; i += 8) {
        float v = 0.f;
        if (n0 + tx < Ntot) v = W[(size_t)(k0 + i) * Ntot + n0 + tx];
        tile[i][tx] = v;
    }
    __syncthreads();
#pragma unroll
    for (int i = ty; i < 32; i += 8) {
        if (n0 + i < Ntot) {
            float v = tile[tx][i];
            __nv_bfloat16 hi = __float2bfloat16_rn(v);
            float lo = v - __bfloat162float(hi);
            size_t o = (size_t)(n0 + i) * K + k0 + tx;
            Thi[o] = hi;
            Tlo[o] = __float2bfloat16_rn(lo);
        }
    }
}

// ------------------------- HMMA bf16-split GEMM ------------------------------
#define KC       32
#define NCHUNK   (FIN / KC)        /* 32 */
#define STRIDE   20                /* uint32 per smem row (16 data + 4 pad) */

__device__ __forceinline__ uint32_t smem_u32(const void* p) {
    uint32_t a;
    asm("{ .reg .u64 t; cvta.to.shared.u64 t, %1; cvt.u32.u64 %0, t; }"
        : "=r"(a) : "l"(p));
    return a;
}
__device__ __forceinline__ void cp16(uint32_t saddr, const void* g, int src_sz) {
    asm volatile("cp.async.cg.shared.global [%0], [%1], 16, %2;"
                 :: "r"(saddr), "l"(g), "r"(src_sz));
}
__device__ __forceinline__ void ldm_x4(uint32_t& r0, uint32_t& r1,
                                       uint32_t& r2, uint32_t& r3, uint32_t addr) {
    asm volatile("ldmatrix.sync.aligned.m8n8.x4.shared.b16 {%0,%1,%2,%3}, [%4];"
                 : "=r"(r0), "=r"(r1), "=r"(r2), "=r"(r3) : "r"(addr));
}
__device__ __forceinline__ void mma_bf16(float& c0, float& c1, float& c2, float& c3,
                                         uint32_t a0, uint32_t a1, uint32_t a2,
                                         uint32_t a3, uint32_t b0, uint32_t b1) {
    asm volatile(
        "mma.sync.aligned.m16n8k16.row.col.f32.bf16.bf16.f32 "
        "{%0,%1,%2,%3}, {%4,%5,%6,%7}, {%8,%9}, {%0,%1,%2,%3};"
        : "+f"(c0), "+f"(c1), "+f"(c2), "+f"(c3)
        : "r"(a0), "r"(a1), "r"(a2), "r"(a3), "r"(b0), "r"(b1));
}

// C[M x Nn] = A[M x FIN] @ BT[Nn x FIN]^T + bias[Nn]
// N tile = NTI*32 per CTA. If splitN>0, CTAs with colBase>=splitN write to Cb
// at column (col - splitN); both outputs use row stride ldC.
template<int NTI>
__global__ __launch_bounds__(256) void gemm_mma(
    const __nv_bfloat16* __restrict__ Ahi, const __nv_bfloat16* __restrict__ Alo,
    const __nv_bfloat16* __restrict__ BThi, const __nv_bfloat16* __restrict__ BTlo,
    const float* __restrict__ bias, float* __restrict__ C,
    float* __restrict__ Cb, int splitN,
    int M, int Nn, int ldC)
{
    constexpr int BUFA = 128 * STRIDE;
    constexpr int BUFB = NTI * 32 * STRIDE;
    constexpr int O_AHI = 0;
    constexpr int O_ALO = BUFA;
    constexpr int O_BHI = 2 * BUFA;
    constexpr int O_BLO = 2 * BUFA + BUFB;
    constexpr int STG   = 2 * BUFA + 2 * BUFB;    // u32 per stage

    extern __shared__ uint32_t smem[];
    const uint32_t sbase = smem_u32(smem);
    const int t = threadIdx.x;
    const int w = t >> 5;
    const int lane = t & 31;
    const int gid = lane >> 2;
    const int tg  = lane & 3;
    const int warpM = w & 1;
    const int warpN = w >> 1;
    const int rowBase = blockIdx.y * 128;
    const int colBase = blockIdx.x * (NTI * 32);

    const int a_row = (lane & 7) + ((lane >> 3) & 1) * 8;
    const int a_kh  = (lane >> 4) & 1;
    const int b_row = (lane & 7) + ((lane >> 4) & 1) * 8;
    const int b_kh  = (lane >> 3) & 1;

    auto issue = [&](int c, int s) {
        const int k0 = c * KC;
        const uint32_t base = sbase + s * (STG * 4);
#pragma unroll
        for (int i = 0; i < 2; i++) {
            int idx = t + i * 256;
            int row = idx >> 2;
            int q   = idx & 3;
            uint32_t soff = (uint32_t)(row * STRIDE + q * 4) * 4;
            int ar = rowBase + row;
            int ok = (ar < M) ? 16 : 0;
            int arc = (ar < M) ? ar : 0;
            size_t ga = (size_t)arc * FIN + k0 + q * 8;
            cp16(base + O_AHI * 4 + soff, Ahi + ga, ok);
            cp16(base + O_ALO * 4 + soff, Alo + ga, ok);
        }
#pragma unroll
        for (int i = 0; i < NTI / 2; i++) {
            int idx = t + i * 256;
            int row = idx >> 2;
            int q   = idx & 3;
            uint32_t soff = (uint32_t)(row * STRIDE + q * 4) * 4;
            int br = colBase + row;
            int okb = (br < Nn) ? 16 : 0;
            int brc = (br < Nn) ? br : 0;
            size_t gb = (size_t)brc * FIN + k0 + q * 8;
            cp16(base + O_BHI * 4 + soff, BThi + gb, okb);
            cp16(base + O_BLO * 4 + soff, BTlo + gb, okb);
        }
        asm volatile("cp.async.commit_group;");
    };

    float acc[4][NTI][4];
#pragma unroll
    for (int mt = 0; mt < 4; mt++)
#pragma unroll
        for (int nt = 0; nt < NTI; nt++)
#pragma unroll
            for (int r = 0; r < 4; r++) acc[mt][nt][r] = 0.f;

    issue(0, 0);

    for (int c = 0; c < NCHUNK; c++) {
        if (c + 1 < NCHUNK) {
            issue(c + 1, (c + 1) & 1);
            asm volatile("cp.async.wait_group 1;");
        } else {
            asm volatile("cp.async.wait_group 0;");
        }
        __syncthreads();

        const uint32_t sb = sbase + (c & 1) * (STG * 4);

#pragma unroll
        for (int ks = 0; ks < 2; ks++) {
            uint32_t ah[4][4], al[4][4];
#pragma unroll
            for (int mt = 0; mt < 4; mt++) {
                uint32_t ra = sb + O_AHI * 4 +
                    (uint32_t)(((warpM * 64 + mt * 16 + a_row) * STRIDE) +
                               ks * 8 + a_kh * 4) * 4;
                ldm_x4(ah[mt][0], ah[mt][1], ah[mt][2], ah[mt][3], ra);
                ldm_x4(al[mt][0], al[mt][1], al[mt][2], al[mt][3],
                       ra + (O_ALO - O_AHI) * 4);
            }
            uint32_t bh[NTI][2], bl[NTI][2];
#pragma unroll
            for (int ntp = 0; ntp < NTI / 2; ntp++) {
                uint32_t rb = sb + O_BHI * 4 +
                    (uint32_t)(((warpN * (NTI * 8) + ntp * 16 + b_row) * STRIDE) +
                               ks * 8 + b_kh * 4) * 4;
                ldm_x4(bh[2 * ntp][0], bh[2 * ntp][1],
                       bh[2 * ntp + 1][0], bh[2 * ntp + 1][1], rb);
                ldm_x4(bl[2 * ntp][0], bl[2 * ntp][1],
                       bl[2 * ntp + 1][0], bl[2 * ntp + 1][1],
                       rb + (O_BLO - O_BHI) * 4);
            }
#pragma unroll
            for (int term = 0; term < 3; term++) {
#pragma unroll
                for (int nt = 0; nt < NTI; nt++) {
#pragma unroll
                    for (int mt = 0; mt < 4; mt++) {
                        float* cc = acc[mt][nt];
                        const uint32_t* aa = (term == 2) ? al[mt] : ah[mt];
                        const uint32_t* bb = (term == 1) ? bl[nt] : bh[nt];
                        mma_bf16(cc[0], cc[1], cc[2], cc[3],
                                 aa[0], aa[1], aa[2], aa[3], bb[0], bb[1]);
                    }
                }
            }
        }
        __syncthreads();
    }

    // epilogue — CTA-level output routing (splitN is tile-aligned)
    float* Cuse = C;
    int coff = 0;
    if (splitN > 0 && colBase >= splitN) { Cuse = Cb; coff = splitN; }

#pragma unroll
    for (int mt = 0; mt < 4; mt++) {
        int r0 = rowBase + warpM * 64 + mt * 16 + gid;
        int r1 = r0 + 8;
#pragma unroll
        for (int nt = 0; nt < NTI; nt++) {
            int cb = colBase + warpN * (NTI * 8) + nt * 8 + tg * 2;
            if (cb >= Nn) continue;
            float b0 = bias[cb], b1 = bias[cb + 1];
            int cc = cb - coff;
            if (r0 < M) {
                float2 o = make_float2(acc[mt][nt][0] + b0, acc[mt][nt][1] + b1);
                *(float2*)(Cuse + (size_t)r0 * ldC + cc) = o;
            }
            if (r1 < M) {
                float2 o = make_float2(acc[mt][nt][2] + b0, acc[mt][nt][3] + b1);
                *(float2*)(Cuse + (size_t)r1 * ldC + cc) = o;
            }
        }
    }
}

// ------------------------- CSR build ---------------------------------------
__global__ void k_zero_counts()
{
    int i = blockIdx.x * blockDim.x + threadIdx.x;
    if (i < NNODES) g_count[i] = 0;
}
__global__ void k_count(const int* __restrict__ ei)
{
    int e = blockIdx.x * blockDim.x + threadIdx.x;
    if (e >= ET) return;
    int dst = (e < NEDGES) ? ei[2 * e + 1] : (e - NEDGES);
    atomicAdd(&g_count[dst], 1);
}
__global__ __launch_bounds__(1024) void k_scan()
{
    __shared__ int sh[1024];
    __shared__ int carry;
    int tid = threadIdx.x;
    if (tid == 0) carry = 0;
    __syncthreads();
    for (int base = 0; base < NNODES; base += 1024) {
        int i = base + tid;
        int v = (i < NNODES) ? g_count[i] : 0;
        sh[tid] = v;
        __syncthreads();
        for (int off = 1; off < 1024; off <<= 1) {
            int t = (tid >= off) ? sh[tid - off] : 0;
            __syncthreads();
            sh[tid] += t;
            __syncthreads();
        }
        int excl = carry + sh[tid] - v;
        if (i < NNODES) { g_rowstart[i] = excl; g_cursor[i] = excl; }
        __syncthreads();
        if (tid == 1023) carry += sh[1023];
        __syncthreads();
    }
    if (tid == 0) g_rowstart[NNODES] = carry;
}
__global__ void k_scatter(const int* __restrict__ ei)
{
    int e = blockIdx.x * blockDim.x + threadIdx.x;
    if (e >= ET) return;
    int src, dst;
    if (e < NEDGES) { src = ei[2 * e]; dst = ei[2 * e + 1]; }
    else            { src = dst = e - NEDGES; }
    int pos = atomicAdd(&g_cursor[dst], 1);
    g_csr[pos] = src;
}

// ------------------------- fused scores + softmax + aggregate ---------------
__global__ __launch_bounds__(128) void node_fused(
    const float* __restrict__ att, const float* __restrict__ bias)
{
    __shared__ float4 satt[HC / 4];      // 12 KB
    __shared__ float  red[4][NH];

    const int node = blockIdx.x;
    const int t = threadIdx.x;
    const int w = t >> 5;
    const int lane = t & 31;

    for (int i = t; i < HC / 4; i += 128)
        satt[i] = ((const float4*)att)[i];

    const int beg = g_rowstart[node];
    const int end = g_rowstart[node + 1];

    float4 xr[NH][2];
    {
        const float4* xrp = (const float4*)(g_xr + (size_t)node * HC);
#pragma unroll
        for (int h = 0; h < NH; h++)
#pragma unroll
            for (int q = 0; q < 2; q++)
                xr[h][q] = xrp[h * 256 + t + 128 * q];
    }
    __syncthreads();

    float m[NH], d[NH];
    float4 acc[NH][2];
#pragma unroll
    for (int h = 0; h < NH; h++) {
        m[h] = -3.0e38f;
        d[h] = 0.f;
#pragma unroll
        for (int q = 0; q < 2; q++) acc[h][q] = make_float4(0.f, 0.f, 0.f, 0.f);
    }

    float4 cur[NH][2];
    if (beg < end) {
        const float4* xlp = (const float4*)(g_xl + (size_t)g_csr[beg] * HC);
#pragma unroll
        for (int h = 0; h < NH; h++)
#pragma unroll
            for (int q = 0; q < 2; q++)
                cur[h][q] = xlp[h * 256 + t + 128 * q];
    }

    for (int p = beg; p < end; p++) {
        float4 nxt[NH][2];
        if (p + 1 < end) {
            const float4* xln = (const float4*)(g_xl + (size_t)g_csr[p + 1] * HC);
#pragma unroll
            for (int h = 0; h < NH; h++)
#pragma unroll
                for (int q = 0; q < 2; q++)
                    nxt[h][q] = xln[h * 256 + t + 128 * q];
        }

        float part[NH];
#pragma unroll
        for (int h = 0; h < NH; h++) {
            part[h] = 0.f;
#pragma unroll
            for (int q = 0; q < 2; q++) {
                float4 v = cur[h][q];
                float4 r = xr[h][q];
                float4 a = satt[h * 256 + t + 128 * q];
                float sx = v.x + r.x; sx = sx > 0.f ? sx : 0.2f * sx;
                float sy = v.y + r.y; sy = sy > 0.f ? sy : 0.2f * sy;
                float sz = v.z + r.z; sz = sz > 0.f ? sz : 0.2f * sz;
                float sw = v.w + r.w; sw = sw > 0.f ? sw : 0.2f * sw;
                part[h] += sx * a.x + sy * a.y + sz * a.z + sw * a.w;
            }
        }
#pragma unroll
        for (int off = 16; off; off >>= 1)
#pragma unroll
            for (int h = 0; h < NH; h++)
                part[h] += __shfl_xor_sync(0xFFFFFFFFu, part[h], off);
        if (lane == 0)
#pragma unroll
            for (int h = 0; h < NH; h++) red[w][h] = part[h];
        __syncthreads();

        float s[NH];
#pragma unroll
        for (int h = 0; h < NH; h++)
            s[h] = red[0][h] + red[1][h] + red[2][h] + red[3][h];
        __syncthreads();

#pragma unroll
        for (int h = 0; h < NH; h++) {
            float e;
            if (s[h] > m[h]) {
                float sc = __expf(m[h] - s[h]);
                d[h] *= sc;
#pragma unroll
                for (int q = 0; q < 2; q++) {
                    acc[h][q].x *= sc; acc[h][q].y *= sc;
                    acc[h][q].z *= sc; acc[h][q].w *= sc;
                }
                m[h] = s[h];
                e = 1.f;
            } else {
                e = __expf(s[h] - m[h]);
            }
            d[h] += e;
#pragma unroll
            for (int q = 0; q < 2; q++) {
                acc[h][q].x += e * cur[h][q].x;
                acc[h][q].y += e * cur[h][q].y;
                acc[h][q].z += e * cur[h][q].z;
                acc[h][q].w += e * cur[h][q].w;
            }
        }

        if (p + 1 < end) {
#pragma unroll
            for (int h = 0; h < NH; h++)
#pragma unroll
                for (int q = 0; q < 2; q++)
                    cur[h][q] = nxt[h][q];
        }
    }

    float invd[NH];
#pragma unroll
    for (int h = 0; h < NH; h++) invd[h] = 1.f / (d[h] + 1e-16f);

    const float inv3 = 1.0f / 3.0f;
#pragma unroll
    for (int q = 0; q < 2; q++) {
        int f = t + 128 * q;
        float o[4];
        o[0] = (acc[0][q].x * invd[0] + acc[1][q].x * invd[1] + acc[2][q].x * invd[2]) * inv3 + bias[4 * f + 0];
        o[1] = (acc[0][q].y * invd[0] + acc[1][q].y * invd[1] + acc[2][q].y * invd[2]) * inv3 + bias[4 * f + 1];
        o[2] = (acc[0][q].z * invd[0] + acc[1][q].z * invd[1] + acc[2][q].z * invd[2]) * inv3 + bias[4 * f + 2];
        o[3] = (acc[0][q].w * invd[0] + acc[1][q].w * invd[1] + acc[2][q].w * invd[2]) * inv3 + bias[4 * f + 3];
        __nv_bfloat16 hi[4], lo[4];
#pragma unroll
        for (int j = 0; j < 4; j++) {
            hi[j] = __float2bfloat16_rn(o[j]);
            lo[j] = __float2bfloat16_rn(o[j] - __bfloat162float(hi[j]));
        }
        size_t idx = (size_t)node * CH + 4 * f;
        *(uint2*)(g_hmhi + idx) = *(uint2*)hi;
        *(uint2*)(g_hmlo + idx) = *(uint2*)lo;
    }
}

// ------------------------- pass-through copies (single launch) ---------------
__global__ void k_copy_both(const float4* __restrict__ s1, float4* __restrict__ d1,
                            int n1, const float4* __restrict__ s2,
                            float4* __restrict__ d2, int n2)
{
    int i = blockIdx.x * blockDim.x + threadIdx.x;
    if (i < n1) d1[i] = s1[i];
    else if (i < n1 + n2) d2[i - n1] = s2[i - n1];
}

// ------------------------- launch ------------------------------------------
extern "C" void kernel_launch(void* const* d_in, const int* in_sizes, int n_in,
                              void* d_out, int out_size)
{
    const float* x    = (const float*)d_in[0];
    const int*   ei   = (const int*)d_in[1];
    const float* Wl   = (const float*)d_in[2];
    const float* bl   = (const float*)d_in[3];
    const float* Wr   = (const float*)d_in[4];
    const float* br   = (const float*)d_in[5];
    const float* att  = (const float*)d_in[6];
    const float* bias = (const float*)d_in[7];
    const float* Wfc  = (const float*)d_in[8];
    const float* bfc  = (const float*)d_in[9];
    const float* exps   = (const float*)d_in[10];
    const float* exps_c = (const float*)d_in[11];
    float* out = (float*)d_out;

    constexpr int SMEM4 = 2 * (2 * 128 * STRIDE + 2 * 128 * STRIDE) * 4; // 81920
    constexpr int SMEM2 = 2 * (2 * 128 * STRIDE + 2 * 64 * STRIDE) * 4;  // 61440
    cudaFuncSetAttribute(gemm_mma<4>, cudaFuncAttributeMaxDynamicSharedMemorySize,
                         SMEM4);
    cudaFuncSetAttribute(gemm_mma<2>, cudaFuncAttributeMaxDynamicSharedMemorySize,
                         SMEM2);

    // device addresses (NOT host shadow symbols — GB300 ATS trap)
    float *pxl, *pxr, *pbcat;
    __nv_bfloat16 *pxhi, *pxlo, *pwThi, *pwTlo;
    __nv_bfloat16 *phmhi, *phmlo, *pfcThi, *pfcTlo;
    cudaGetSymbolAddress((void**)&pxl,    g_xl);
    cudaGetSymbolAddress((void**)&pxr,    g_xr);
    cudaGetSymbolAddress((void**)&pbcat,  g_bcat);
    cudaGetSymbolAddress((void**)&pxhi,   g_xhi);
    cudaGetSymbolAddress((void**)&pxlo,   g_xlo);
    cudaGetSymbolAddress((void**)&pwThi,  g_wThi);
    cudaGetSymbolAddress((void**)&pwTlo,  g_wTlo);
    cudaGetSymbolAddress((void**)&phmhi,  g_hmhi);
    cudaGetSymbolAddress((void**)&phmlo,  g_hmlo);
    cudaGetSymbolAddress((void**)&pfcThi, g_wfcThi);
    cudaGetSymbolAddress((void**)&pfcTlo, g_wfcTlo);

    // #1: x split + bias concat
    x_split<<<(NNODES * FIN + 255) / 256, 256>>>(x, bl, br);
    // #2, #3: weight splits (WlT rows [0,HC), WrT rows [HC,2HC))
    {
        dim3 grid(HC / 32, FIN / 32);
        w_splitT_g<<<grid, 256>>>(Wl, pwThi, pwTlo, HC, FIN);
        w_splitT_g<<<grid, 256>>>(Wr, pwThi + (size_t)HC * FIN,
                                      pwTlo + (size_t)HC * FIN, HC, FIN);
    }

    // #4: BOTH projections in ONE launch (this is the profiled launch slot)
    {
        dim3 grid((2 * HC) / 128, (NNODES + 127) / 128);
        gemm_mma<4><<<grid, 256, SMEM4>>>(pxhi, pxlo, pwThi, pwTlo,
                                          pbcat, pxl, pxr, HC,
                                          NNODES, 2 * HC, HC);
    }

    // CSR by destination
    k_zero_counts<<<(NNODES + 255) / 256, 256>>>();
    k_count<<<(ET + 255) / 256, 256>>>(ei);
    k_scan<<<1, 1024>>>();
    k_scatter<<<(ET + 255) / 256, 256>>>(ei);

    // fused scores + online softmax + aggregation + head mean + bias
    node_fused<<<NNODES, 128>>>(att, bias);

    // fc weight split (deferred — only needed here)
    {
        dim3 grid((NCLS + 31) / 32, CH / 32);
        w_splitT_g<<<grid, 256>>>(Wfc, pfcThi, pfcTlo, NCLS, CH);
    }

    // fc readout: narrow N tile (64) to cut the tail
    {
        dim3 grid((NCLS + 63) / 64, (NNODES + 127) / 128);
        gemm_mma<2><<<grid, 256, SMEM2>>>(phmhi, phmlo, pfcThi, pfcTlo,
                                          bfc, out, nullptr, 0,
                                          NNODES, NCLS, NCLS);
    }

    // pass-through outputs (one launch)
    size_t hElems = (size_t)NNODES * NCLS;
    int n4a = in_sizes[10] / 4;
    int n4b = in_sizes[11] / 4;
    k_copy_both<<<(n4a + n4b + 255) / 256, 256>>>(
        (const float4*)exps, (float4*)(out + hElems), n4a,
        (const float4*)exps_c, (float4*)(out + hElems + in_sizes[10]), n4b);
}

// round 16
// speedup vs baseline: 1.2910x; 1.1666x over previous
#include <cuda_runtime.h>
#include <cuda_bf16.h>
#include <math.h>
#include <stdint.h>

#define NNODES 10000
#define NEDGES 100000
#define NH     3
#define CH     1024
#define HC     3072          /* NH*CH */
#define ET     110000        /* NEDGES + NNODES self loops */
#define NCLS   460
#define FIN    1024

// ------------------------- scratch (device globals, no allocs) -------------
__device__ float g_xl[(size_t)NNODES * HC];
__device__ float g_xr[(size_t)NNODES * HC];
__device__ int   g_count[NNODES];
__device__ int   g_rowstart[NNODES + 1];
__device__ int   g_cursor[NNODES];
__device__ int   g_csr[ET];                      // stores SRC node per slot
// bf16 hi/lo splits
__device__ __nv_bfloat16 g_xhi[(size_t)NNODES * FIN];
__device__ __nv_bfloat16 g_xlo[(size_t)NNODES * FIN];
__device__ __nv_bfloat16 g_wThi[(size_t)2 * HC * FIN];  // [WlT ; WrT] concat
__device__ __nv_bfloat16 g_wTlo[(size_t)2 * HC * FIN];
__device__ float         g_bcat[2 * HC];                // bl || br
__device__ __nv_bfloat16 g_hmhi[(size_t)NNODES * CH];
__device__ __nv_bfloat16 g_hmlo[(size_t)NNODES * CH];
__device__ __nv_bfloat16 g_wfcThi[(size_t)512 * CH];
__device__ __nv_bfloat16 g_wfcTlo[(size_t)512 * CH];

// ------------------------- split/transpose prep -----------------------------
__global__ void x_split(const float* __restrict__ x,
                        const float* __restrict__ bl,
                        const float* __restrict__ br)
{
    int i = blockIdx.x * blockDim.x + threadIdx.x;
    if (i < 2 * HC)
        g_bcat[i] = (i < HC) ? bl[i] : br[i - HC];
    if (i >= NNODES * FIN) return;
    float v = x[i];
    __nv_bfloat16 hi = __float2bfloat16_rn(v);
    float lo = v - __bfloat162float(hi);
    g_xhi[i] = hi;
    g_xlo[i] = __float2bfloat16_rn(lo);
}

// W [K][Ntot] -> T hi/lo [Ntot][K]  (generalized, clamped)
__global__ __launch_bounds__(256) void w_splitT_g(
    const float* __restrict__ W, __nv_bfloat16* __restrict__ Thi,
    __nv_bfloat16* __restrict__ Tlo, int Ntot, int K)
{
    __shared__ float tile[32][33];
    int tx = threadIdx.x & 31;
    int ty = threadIdx.x >> 5;
    int n0 = blockIdx.x * 32;
    int k0 = blockIdx.y * 32;
#pragma unroll
    for (int i = ty; i < 32; i += 8) {
        float v = 0.f;
        if (n0 + tx < Ntot) v = W[(size_t)(k0 + i) * Ntot + n0 + tx];
        tile[i][tx] = v;
    }
    __syncthreads();
#pragma unroll
    for (int i = ty; i < 32; i += 8) {
        if (n0 + i < Ntot) {
            float v = tile[tx][i];
            __nv_bfloat16 hi = __float2bfloat16_rn(v);
            float lo = v - __bfloat162float(hi);
            size_t o = (size_t)(n0 + i) * K + k0 + tx;
            Thi[o] = hi;
            Tlo[o] = __float2bfloat16_rn(lo);
        }
    }
}

// ------------------------- HMMA bf16-split GEMM ------------------------------
#define KC       32
#define NCHUNK   (FIN / KC)        /* 32 */
#define STRIDE   16                /* u32 per row, padless; XOR chunk swizzle */
#define NSTAGE   3
// 16B-chunk swizzle: logical chunk q (0..3) of row r lives at q ^ ((r>>1)&3)
#define SWQ(r, q) ((q) ^ (((r) >> 1) & 3))

__device__ __forceinline__ uint32_t smem_u32(const void* p) {
    uint32_t a;
    asm("{ .reg .u64 t; cvta.to.shared.u64 t, %1; cvt.u32.u64 %0, t; }"
        : "=r"(a) : "l"(p));
    return a;
}
__device__ __forceinline__ void cp16(uint32_t saddr, const void* g, int src_sz) {
    asm volatile("cp.async.cg.shared.global [%0], [%1], 16, %2;"
                 :: "r"(saddr), "l"(g), "r"(src_sz));
}
__device__ __forceinline__ void ldm_x4(uint32_t& r0, uint32_t& r1,
                                       uint32_t& r2, uint32_t& r3, uint32_t addr) {
    asm volatile("ldmatrix.sync.aligned.m8n8.x4.shared.b16 {%0,%1,%2,%3}, [%4];"
                 : "=r"(r0), "=r"(r1), "=r"(r2), "=r"(r3) : "r"(addr));
}
__device__ __forceinline__ void mma_bf16(float& c0, float& c1, float& c2, float& c3,
                                         uint32_t a0, uint32_t a1, uint32_t a2,
                                         uint32_t a3, uint32_t b0, uint32_t b1) {
    asm volatile(
        "mma.sync.aligned.m16n8k16.row.col.f32.bf16.bf16.f32 "
        "{%0,%1,%2,%3}, {%4,%5,%6,%7}, {%8,%9}, {%0,%1,%2,%3};"
        : "+f"(c0), "+f"(c1), "+f"(c2), "+f"(c3)
        : "r"(a0), "r"(a1), "r"(a2), "r"(a3), "r"(b0), "r"(b1));
}

// C[M x Nn] = A[M x FIN] @ BT[Nn x FIN]^T + bias[Nn]
// 3-stage cp.async pipeline, ONE __syncthreads per K-chunk, swizzled smem.
template<int NTI>
__global__ __launch_bounds__(256) void gemm_mma(
    const __nv_bfloat16* __restrict__ Ahi, const __nv_bfloat16* __restrict__ Alo,
    const __nv_bfloat16* __restrict__ BThi, const __nv_bfloat16* __restrict__ BTlo,
    const float* __restrict__ bias, float* __restrict__ C,
    float* __restrict__ Cb, int splitN,
    int M, int Nn, int ldC)
{
    constexpr int BUFA = 128 * STRIDE;
    constexpr int BUFB = NTI * 32 * STRIDE;
    constexpr int O_AHI = 0;
    constexpr int O_ALO = BUFA;
    constexpr int O_BHI = 2 * BUFA;
    constexpr int O_BLO = 2 * BUFA + BUFB;
    constexpr int STG   = 2 * BUFA + 2 * BUFB;    // u32 per stage

    extern __shared__ uint32_t smem[];
    const uint32_t sbase = smem_u32(smem);
    const int t = threadIdx.x;
    const int w = t >> 5;
    const int lane = t & 31;
    const int gid = lane >> 2;
    const int tg  = lane & 3;
    const int warpM = w & 1;
    const int warpN = w >> 1;
    const int rowBase = blockIdx.y * 128;
    const int colBase = blockIdx.x * (NTI * 32);

    const int a_row = (lane & 7) + ((lane >> 3) & 1) * 8;
    const int a_kh  = (lane >> 4) & 1;
    const int b_row = (lane & 7) + ((lane >> 4) & 1) * 8;
    const int b_kh  = (lane >> 3) & 1;

    auto issue = [&](int c, int s) {
        const int k0 = c * KC;
        const uint32_t base = sbase + s * (STG * 4);
#pragma unroll
        for (int i = 0; i < 2; i++) {
            int idx = t + i * 256;
            int row = idx >> 2;
            int q   = idx & 3;
            uint32_t soff = (uint32_t)(row * STRIDE + SWQ(row, q) * 4) * 4;
            int ar = rowBase + row;
            int ok = (ar < M) ? 16 : 0;
            int arc = (ar < M) ? ar : 0;
            size_t ga = (size_t)arc * FIN + k0 + q * 8;
            cp16(base + O_AHI * 4 + soff, Ahi + ga, ok);
            cp16(base + O_ALO * 4 + soff, Alo + ga, ok);
        }
#pragma unroll
        for (int i = 0; i < NTI / 2; i++) {
            int idx = t + i * 256;
            int row = idx >> 2;
            int q   = idx & 3;
            uint32_t soff = (uint32_t)(row * STRIDE + SWQ(row, q) * 4) * 4;
            int br = colBase + row;
            int okb = (br < Nn) ? 16 : 0;
            int brc = (br < Nn) ? br : 0;
            size_t gb = (size_t)brc * FIN + k0 + q * 8;
            cp16(base + O_BHI * 4 + soff, BThi + gb, okb);
            cp16(base + O_BLO * 4 + soff, BTlo + gb, okb);
        }
        asm volatile("cp.async.commit_group;");
    };

    float acc[4][NTI][4];
#pragma unroll
    for (int mt = 0; mt < 4; mt++)
#pragma unroll
        for (int nt = 0; nt < NTI; nt++)
#pragma unroll
            for (int r = 0; r < 4; r++) acc[mt][nt][r] = 0.f;

    issue(0, 0);
    issue(1, 1);

    for (int c = 0; c < NCHUNK; c++) {
        asm volatile("cp.async.wait_group 1;");
        __syncthreads();   // all warps done with chunk c-1 -> stage free

        if (c + 2 < NCHUNK) issue(c + 2, (c + 2) % NSTAGE);

        const uint32_t sb = sbase + (c % NSTAGE) * (STG * 4);

#pragma unroll
        for (int ks = 0; ks < 2; ks++) {
            uint32_t ah[4][4], al[4][4];
#pragma unroll
            for (int mt = 0; mt < 4; mt++) {
                int ra_row = warpM * 64 + mt * 16 + a_row;
                int chunk  = ks * 2 + a_kh;
                uint32_t ra = sb + O_AHI * 4 +
                    (uint32_t)(ra_row * STRIDE + SWQ(ra_row, chunk) * 4) * 4;
                ldm_x4(ah[mt][0], ah[mt][1], ah[mt][2], ah[mt][3], ra);
                ldm_x4(al[mt][0], al[mt][1], al[mt][2], al[mt][3],
                       ra + (O_ALO - O_AHI) * 4);
            }
            uint32_t bh[NTI][2], bl[NTI][2];
#pragma unroll
            for (int ntp = 0; ntp < NTI / 2; ntp++) {
                int rb_row = warpN * (NTI * 8) + ntp * 16 + b_row;
                int chunk  = ks * 2 + b_kh;
                uint32_t rb = sb + O_BHI * 4 +
                    (uint32_t)(rb_row * STRIDE + SWQ(rb_row, chunk) * 4) * 4;
                ldm_x4(bh[2 * ntp][0], bh[2 * ntp][1],
                       bh[2 * ntp + 1][0], bh[2 * ntp + 1][1], rb);
                ldm_x4(bl[2 * ntp][0], bl[2 * ntp][1],
                       bl[2 * ntp + 1][0], bl[2 * ntp + 1][1],
                       rb + (O_BLO - O_BHI) * 4);
            }
#pragma unroll
            for (int term = 0; term < 3; term++) {
#pragma unroll
                for (int nt = 0; nt < NTI; nt++) {
#pragma unroll
                    for (int mt = 0; mt < 4; mt++) {
                        float* cc = acc[mt][nt];
                        const uint32_t* aa = (term == 2) ? al[mt] : ah[mt];
                        const uint32_t* bb = (term == 1) ? bl[nt] : bh[nt];
                        mma_bf16(cc[0], cc[1], cc[2], cc[3],
                                 aa[0], aa[1], aa[2], aa[3], bb[0], bb[1]);
                    }
                }
            }
        }
    }

    // epilogue — CTA-level output routing (splitN is tile-aligned)
    float* Cuse = C;
    int coff = 0;
    if (splitN > 0 && colBase >= splitN) { Cuse = Cb; coff = splitN; }

#pragma unroll
    for (int mt = 0; mt < 4; mt++) {
        int r0 = rowBase + warpM * 64 + mt * 16 + gid;
        int r1 = r0 + 8;
#pragma unroll
        for (int nt = 0; nt < NTI; nt++) {
            int cb = colBase + warpN * (NTI * 8) + nt * 8 + tg * 2;
            if (cb >= Nn) continue;
            float b0 = bias[cb], b1 = bias[cb + 1];
            int cc = cb - coff;
            if (r0 < M) {
                float2 o = make_float2(acc[mt][nt][0] + b0, acc[mt][nt][1] + b1);
                *(float2*)(Cuse + (size_t)r0 * ldC + cc) = o;
            }
            if (r1 < M) {
                float2 o = make_float2(acc[mt][nt][2] + b0, acc[mt][nt][3] + b1);
                *(float2*)(Cuse + (size_t)r1 * ldC + cc) = o;
            }
        }
    }
}

// ------------------------- CSR build ---------------------------------------
__global__ void k_zero_counts()
{
    int i = blockIdx.x * blockDim.x + threadIdx.x;
    if (i < NNODES) g_count[i] = 0;
}
__global__ void k_count(const int* __restrict__ ei)
{
    int e = blockIdx.x * blockDim.x + threadIdx.x;
    if (e >= ET) return;
    int dst = (e < NEDGES) ? ei[2 * e + 1] : (e - NEDGES);
    atomicAdd(&g_count[dst], 1);
}
__global__ __launch_bounds__(1024) void k_scan()
{
    __shared__ int sh[1024];
    __shared__ int carry;
    int tid = threadIdx.x;
    if (tid == 0) carry = 0;
    __syncthreads();
    for (int base = 0; base < NNODES; base += 1024) {
        int i = base + tid;
        int v = (i < NNODES) ? g_count[i] : 0;
        sh[tid] = v;
        __syncthreads();
        for (int off = 1; off < 1024; off <<= 1) {
            int t = (tid >= off) ? sh[tid - off] : 0;
            __syncthreads();
            sh[tid] += t;
            __syncthreads();
        }
        int excl = carry + sh[tid] - v;
        if (i < NNODES) { g_rowstart[i] = excl; g_cursor[i] = excl; }
        __syncthreads();
        if (tid == 1023) carry += sh[1023];
        __syncthreads();
    }
    if (tid == 0) g_rowstart[NNODES] = carry;
}
__global__ void k_scatter(const int* __restrict__ ei)
{
    int e = blockIdx.x * blockDim.x + threadIdx.x;
    if (e >= ET) return;
    int src, dst;
    if (e < NEDGES) { src = ei[2 * e]; dst = ei[2 * e + 1]; }
    else            { src = dst = e - NEDGES; }
    int pos = atomicAdd(&g_cursor[dst], 1);
    g_csr[pos] = src;
}

// ------------------------- fused scores + softmax + aggregate ---------------
__global__ __launch_bounds__(128) void node_fused(
    const float* __restrict__ att, const float* __restrict__ bias)
{
    __shared__ float4 satt[HC / 4];      // 12 KB
    __shared__ float  red[4][NH];

    const int node = blockIdx.x;
    const int t = threadIdx.x;
    const int w = t >> 5;
    const int lane = t & 31;

    for (int i = t; i < HC / 4; i += 128)
        satt[i] = ((const float4*)att)[i];

    const int beg = g_rowstart[node];
    const int end = g_rowstart[node + 1];

    float4 xr[NH][2];
    {
        const float4* xrp = (const float4*)(g_xr + (size_t)node * HC);
#pragma unroll
        for (int h = 0; h < NH; h++)
#pragma unroll
            for (int q = 0; q < 2; q++)
                xr[h][q] = xrp[h * 256 + t + 128 * q];
    }
    __syncthreads();

    float m[NH], d[NH];
    float4 acc[NH][2];
#pragma unroll
    for (int h = 0; h < NH; h++) {
        m[h] = -3.0e38f;
        d[h] = 0.f;
#pragma unroll
        for (int q = 0; q < 2; q++) acc[h][q] = make_float4(0.f, 0.f, 0.f, 0.f);
    }

    float4 cur[NH][2];
    if (beg < end) {
        const float4* xlp = (const float4*)(g_xl + (size_t)g_csr[beg] * HC);
#pragma unroll
        for (int h = 0; h < NH; h++)
#pragma unroll
            for (int q = 0; q < 2; q++)
                cur[h][q] = xlp[h * 256 + t + 128 * q];
    }

    for (int p = beg; p < end; p++) {
        float4 nxt[NH][2];
        if (p + 1 < end) {
            const float4* xln = (const float4*)(g_xl + (size_t)g_csr[p + 1] * HC);
#pragma unroll
            for (int h = 0; h < NH; h++)
#pragma unroll
                for (int q = 0; q < 2; q++)
                    nxt[h][q] = xln[h * 256 + t + 128 * q];
        }

        float part[NH];
#pragma unroll
        for (int h = 0; h < NH; h++) {
            part[h] = 0.f;
#pragma unroll
            for (int q = 0; q < 2; q++) {
                float4 v = cur[h][q];
                float4 r = xr[h][q];
                float4 a = satt[h * 256 + t + 128 * q];
                float sx = v.x + r.x; sx = sx > 0.f ? sx : 0.2f * sx;
                float sy = v.y + r.y; sy = sy > 0.f ? sy : 0.2f * sy;
                float sz = v.z + r.z; sz = sz > 0.f ? sz : 0.2f * sz;
                float sw = v.w + r.w; sw = sw > 0.f ? sw : 0.2f * sw;
                part[h] += sx * a.x + sy * a.y + sz * a.z + sw * a.w;
            }
        }
#pragma unroll
        for (int off = 16; off; off >>= 1)
#pragma unroll
            for (int h = 0; h < NH; h++)
                part[h] += __shfl_xor_sync(0xFFFFFFFFu, part[h], off);
        if (lane == 0)
#pragma unroll
            for (int h = 0; h < NH; h++) red[w][h] = part[h];
        __syncthreads();

        float s[NH];
#pragma unroll
        for (int h = 0; h < NH; h++)
            s[h] = red[0][h] + red[1][h] + red[2][h] + red[3][h];
        __syncthreads();

#pragma unroll
        for (int h = 0; h < NH; h++) {
            float e;
            if (s[h] > m[h]) {
                float sc = __expf(m[h] - s[h]);
                d[h] *= sc;
#pragma unroll
                for (int q = 0; q < 2; q++) {
                    acc[h][q].x *= sc; acc[h][q].y *= sc;
                    acc[h][q].z *= sc; acc[h][q].w *= sc;
                }
                m[h] = s[h];
                e = 1.f;
            } else {
                e = __expf(s[h] - m[h]);
            }
            d[h] += e;
#pragma unroll
            for (int q = 0; q < 2; q++) {
                acc[h][q].x += e * cur[h][q].x;
                acc[h][q].y += e * cur[h][q].y;
                acc[h][q].z += e * cur[h][q].z;
                acc[h][q].w += e * cur[h][q].w;
            }
        }

        if (p + 1 < end) {
#pragma unroll
            for (int h = 0; h < NH; h++)
#pragma unroll
                for (int q = 0; q < 2; q++)
                    cur[h][q] = nxt[h][q];
        }
    }

    float invd[NH];
#pragma unroll
    for (int h = 0; h < NH; h++) invd[h] = 1.f / (d[h] + 1e-16f);

    const float inv3 = 1.0f / 3.0f;
#pragma unroll
    for (int q = 0; q < 2; q++) {
        int f = t + 128 * q;
        float o[4];
        o[0] = (acc[0][q].x * invd[0] + acc[1][q].x * invd[1] + acc[2][q].x * invd[2]) * inv3 + bias[4 * f + 0];
        o[1] = (acc[0][q].y * invd[0] + acc[1][q].y * invd[1] + acc[2][q].y * invd[2]) * inv3 + bias[4 * f + 1];
        o[2] = (acc[0][q].z * invd[0] + acc[1][q].z * invd[1] + acc[2][q].z * invd[2]) * inv3 + bias[4 * f + 2];
        o[3] = (acc[0][q].w * invd[0] + acc[1][q].w * invd[1] + acc[2][q].w * invd[2]) * inv3 + bias[4 * f + 3];
        __nv_bfloat16 hi[4], lo[4];
#pragma unroll
        for (int j = 0; j < 4; j++) {
            hi[j] = __float2bfloat16_rn(o[j]);
            lo[j] = __float2bfloat16_rn(o[j] - __bfloat162float(hi[j]));
        }
        size_t idx = (size_t)node * CH + 4 * f;
        *(uint2*)(g_hmhi + idx) = *(uint2*)hi;
        *(uint2*)(g_hmlo + idx) = *(uint2*)lo;
    }
}

// ------------------------- pass-through copies (single launch) ---------------
__global__ void k_copy_both(const float4* __restrict__ s1, float4* __restrict__ d1,
                            int n1, const float4* __restrict__ s2,
                            float4* __restrict__ d2, int n2)
{
    int i = blockIdx.x * blockDim.x + threadIdx.x;
    if (i < n1) d1[i] = s1[i];
    else if (i < n1 + n2) d2[i - n1] = s2[i - n1];
}

// ------------------------- launch ------------------------------------------
extern "C" void kernel_launch(void* const* d_in, const int* in_sizes, int n_in,
                              void* d_out, int out_size)
{
    const float* x    = (const float*)d_in[0];
    const int*   ei   = (const int*)d_in[1];
    const float* Wl   = (const float*)d_in[2];
    const float* bl   = (const float*)d_in[3];
    const float* Wr   = (const float*)d_in[4];
    const float* br   = (const float*)d_in[5];
    const float* att  = (const float*)d_in[6];
    const float* bias = (const float*)d_in[7];
    const float* Wfc  = (const float*)d_in[8];
    const float* bfc  = (const float*)d_in[9];
    const float* exps   = (const float*)d_in[10];
    const float* exps_c = (const float*)d_in[11];
    float* out = (float*)d_out;

    constexpr int SMEM4 = NSTAGE * (2 * 128 * STRIDE + 2 * 128 * STRIDE) * 4; // 98304
    constexpr int SMEM2 = NSTAGE * (2 * 128 * STRIDE + 2 * 64 * STRIDE) * 4;  // 73728
    cudaFuncSetAttribute(gemm_mma<4>, cudaFuncAttributeMaxDynamicSharedMemorySize,
                         SMEM4);
    cudaFuncSetAttribute(gemm_mma<2>, cudaFuncAttributeMaxDynamicSharedMemorySize,
                         SMEM2);

    // device addresses (NOT host shadow symbols — GB300 ATS trap)
    float *pxl, *pxr, *pbcat;
    __nv_bfloat16 *pxhi, *pxlo, *pwThi, *pwTlo;
    __nv_bfloat16 *phmhi, *phmlo, *pfcThi, *pfcTlo;
    cudaGetSymbolAddress((void**)&pxl,    g_xl);
    cudaGetSymbolAddress((void**)&pxr,    g_xr);
    cudaGetSymbolAddress((void**)&pbcat,  g_bcat);
    cudaGetSymbolAddress((void**)&pxhi,   g_xhi);
    cudaGetSymbolAddress((void**)&pxlo,   g_xlo);
    cudaGetSymbolAddress((void**)&pwThi,  g_wThi);
    cudaGetSymbolAddress((void**)&pwTlo,  g_wTlo);
    cudaGetSymbolAddress((void**)&phmhi,  g_hmhi);
    cudaGetSymbolAddress((void**)&phmlo,  g_hmlo);
    cudaGetSymbolAddress((void**)&pfcThi, g_wfcThi);
    cudaGetSymbolAddress((void**)&pfcTlo, g_wfcTlo);

    // #1: x split + bias concat
    x_split<<<(NNODES * FIN + 255) / 256, 256>>>(x, bl, br);
    // #2, #3: weight splits (WlT rows [0,HC), WrT rows [HC,2HC))
    {
        dim3 grid(HC / 32, FIN / 32);
        w_splitT_g<<<grid, 256>>>(Wl, pwThi, pwTlo, HC, FIN);
        w_splitT_g<<<grid, 256>>>(Wr, pwThi + (size_t)HC * FIN,
                                      pwTlo + (size_t)HC * FIN, HC, FIN);
    }

    // #4: BOTH projections in ONE launch (profiled slot)
    {
        dim3 grid((2 * HC) / 128, (NNODES + 127) / 128);
        gemm_mma<4><<<grid, 256, SMEM4>>>(pxhi, pxlo, pwThi, pwTlo,
                                          pbcat, pxl, pxr, HC,
                                          NNODES, 2 * HC, HC);
    }

    // CSR by destination
    k_zero_counts<<<(NNODES + 255) / 256, 256>>>();
    k_count<<<(ET + 255) / 256, 256>>>(ei);
    k_scan<<<1, 1024>>>();
    k_scatter<<<(ET + 255) / 256, 256>>>(ei);

    // fused scores + online softmax + aggregation + head mean + bias
    node_fused<<<NNODES, 128>>>(att, bias);

    // fc weight split (deferred — only needed here)
    {
        dim3 grid((NCLS + 31) / 32, CH / 32);
        w_splitT_g<<<grid, 256>>>(Wfc, pfcThi, pfcTlo, NCLS, CH);
    }

    // fc readout: narrow N tile (64)
    {
        dim3 grid((NCLS + 63) / 64, (NNODES + 127) / 128);
        gemm_mma<2><<<grid, 256, SMEM2>>>(phmhi, phmlo, pfcThi, pfcTlo,
                                          bfc, out, nullptr, 0,
                                          NNODES, NCLS, NCLS);
    }

    // pass-through outputs (one launch)
    size_t hElems = (size_t)NNODES * NCLS;
    int n4a = in_sizes[10] / 4;
    int n4b = in_sizes[11] / 4;
    k_copy_both<<<(n4a + n4b + 255) / 256, 256>>>(
        (const float4*)exps, (float4*)(out + hElems), n4a,
        (const float4*)exps_c, (float4*)(out + hElems + in_sizes[10]), n4b);
}

// round 17
// speedup vs baseline: 1.3128x; 1.0169x over previous
#include <cuda_runtime.h>
#include <cuda_bf16.h>
#include <math.h>
#include <stdint.h>

#define NNODES 10000
#define NEDGES 100000
#define NH     3
#define CH     1024
#define HC     3072          /* NH*CH */
#define ET     110000        /* NEDGES + NNODES self loops */
#define NCLS   460
#define FIN    1024

// ------------------------- scratch (device globals, no allocs) -------------
__device__ float g_xl[(size_t)NNODES * HC];
__device__ float g_xr[(size_t)NNODES * HC];
__device__ int   g_count[NNODES];
__device__ int   g_rowstart[NNODES + 1];
__device__ int   g_cursor[NNODES];
__device__ int   g_csr[ET];                      // stores SRC node per slot
// bf16 hi/lo splits
__device__ __nv_bfloat16 g_xhi[(size_t)NNODES * FIN];
__device__ __nv_bfloat16 g_xlo[(size_t)NNODES * FIN];
__device__ __nv_bfloat16 g_wThi[(size_t)2 * HC * FIN];  // [WlT ; WrT] concat
__device__ __nv_bfloat16 g_wTlo[(size_t)2 * HC * FIN];
__device__ float         g_bcat[2 * HC];                // bl || br
__device__ __nv_bfloat16 g_hmhi[(size_t)NNODES * CH];
__device__ __nv_bfloat16 g_hmlo[(size_t)NNODES * CH];
__device__ __nv_bfloat16 g_wfcThi[(size_t)512 * CH];
__device__ __nv_bfloat16 g_wfcTlo[(size_t)512 * CH];

// ------------------------- split/transpose prep -----------------------------
// x split + bias concat + CSR count-array zeroing (zero must precede counting,
// which happens in the NEXT kernel — stream order guarantees it)
__global__ void x_split(const float* __restrict__ x,
                        const float* __restrict__ bl,
                        const float* __restrict__ br)
{
    int i = blockIdx.x * blockDim.x + threadIdx.x;
    if (i < 2 * HC)
        g_bcat[i] = (i < HC) ? bl[i] : br[i - HC];
    if (i < NNODES)
        g_count[i] = 0;
    if (i >= NNODES * FIN) return;
    float v = x[i];
    __nv_bfloat16 hi = __float2bfloat16_rn(v);
    float lo = v - __bfloat162float(hi);
    g_xhi[i] = hi;
    g_xlo[i] = __float2bfloat16_rn(lo);
}

// W [K][Ntot] -> T hi/lo [Ntot][K]  (generalized, clamped)
// If ei != nullptr, also performs the CSR degree count (g_count must be zeroed
// by an earlier kernel).
__global__ __launch_bounds__(256) void w_splitT_g(
    const float* __restrict__ W, __nv_bfloat16* __restrict__ Thi,
    __nv_bfloat16* __restrict__ Tlo, int Ntot, int K,
    const int* __restrict__ ei)
{
    if (ei) {
        int g = (blockIdx.y * gridDim.x + blockIdx.x) * 256 + threadIdx.x;
        if (g < ET) {
            int dst = (g < NEDGES) ? ei[2 * g + 1] : (g - NEDGES);
            atomicAdd(&g_count[dst], 1);
        }
    }

    __shared__ float tile[32][33];
    int tx = threadIdx.x & 31;
    int ty = threadIdx.x >> 5;
    int n0 = blockIdx.x * 32;
    int k0 = blockIdx.y * 32;
#pragma unroll
    for (int i = ty; i < 32; i += 8) {
        float v = 0.f;
        if (n0 + tx < Ntot) v = W[(size_t)(k0 + i) * Ntot + n0 + tx];
        tile[i][tx] = v;
    }
    __syncthreads();
#pragma unroll
    for (int i = ty; i < 32; i += 8) {
        if (n0 + i < Ntot) {
            float v = tile[tx][i];
            __nv_bfloat16 hi = __float2bfloat16_rn(v);
            float lo = v - __bfloat162float(hi);
            size_t o = (size_t)(n0 + i) * K + k0 + tx;
            Thi[o] = hi;
            Tlo[o] = __float2bfloat16_rn(lo);
        }
    }
}

// ------------------------- HMMA bf16-split GEMM ------------------------------
#define KC       32
#define NCHUNK   (FIN / KC)        /* 32 */
#define STRIDE   16                /* u32 per row, padless; XOR chunk swizzle */
#define NSTAGE   3
#define SWQ(r, q) ((q) ^ (((r) >> 1) & 3))

__device__ __forceinline__ uint32_t smem_u32(const void* p) {
    uint32_t a;
    asm("{ .reg .u64 t; cvta.to.shared.u64 t, %1; cvt.u32.u64 %0, t; }"
        : "=r"(a) : "l"(p));
    return a;
}
__device__ __forceinline__ void cp16(uint32_t saddr, const void* g, int src_sz) {
    asm volatile("cp.async.cg.shared.global [%0], [%1], 16, %2;"
                 :: "r"(saddr), "l"(g), "r"(src_sz));
}
__device__ __forceinline__ void ldm_x4(uint32_t& r0, uint32_t& r1,
                                       uint32_t& r2, uint32_t& r3, uint32_t addr) {
    asm volatile("ldmatrix.sync.aligned.m8n8.x4.shared.b16 {%0,%1,%2,%3}, [%4];"
                 : "=r"(r0), "=r"(r1), "=r"(r2), "=r"(r3) : "r"(addr));
}
__device__ __forceinline__ void mma_bf16(float& c0, float& c1, float& c2, float& c3,
                                         uint32_t a0, uint32_t a1, uint32_t a2,
                                         uint32_t a3, uint32_t b0, uint32_t b1) {
    asm volatile(
        "mma.sync.aligned.m16n8k16.row.col.f32.bf16.bf16.f32 "
        "{%0,%1,%2,%3}, {%4,%5,%6,%7}, {%8,%9}, {%0,%1,%2,%3};"
        : "+f"(c0), "+f"(c1), "+f"(c2), "+f"(c3)
        : "r"(a0), "r"(a1), "r"(a2), "r"(a3), "r"(b0), "r"(b1));
}

template<int NTI>
__global__ __launch_bounds__(256) void gemm_mma(
    const __nv_bfloat16* __restrict__ Ahi, const __nv_bfloat16* __restrict__ Alo,
    const __nv_bfloat16* __restrict__ BThi, const __nv_bfloat16* __restrict__ BTlo,
    const float* __restrict__ bias, float* __restrict__ C,
    float* __restrict__ Cb, int splitN,
    int M, int Nn, int ldC)
{
    constexpr int BUFA = 128 * STRIDE;
    constexpr int BUFB = NTI * 32 * STRIDE;
    constexpr int O_AHI = 0;
    constexpr int O_ALO = BUFA;
    constexpr int O_BHI = 2 * BUFA;
    constexpr int O_BLO = 2 * BUFA + BUFB;
    constexpr int STG   = 2 * BUFA + 2 * BUFB;

    extern __shared__ uint32_t smem[];
    const uint32_t sbase = smem_u32(smem);
    const int t = threadIdx.x;
    const int w = t >> 5;
    const int lane = t & 31;
    const int gid = lane >> 2;
    const int tg  = lane & 3;
    const int warpM = w & 1;
    const int warpN = w >> 1;
    const int rowBase = blockIdx.y * 128;
    const int colBase = blockIdx.x * (NTI * 32);

    const int a_row = (lane & 7) + ((lane >> 3) & 1) * 8;
    const int a_kh  = (lane >> 4) & 1;
    const int b_row = (lane & 7) + ((lane >> 4) & 1) * 8;
    const int b_kh  = (lane >> 3) & 1;

    auto issue = [&](int c, int s) {
        const int k0 = c * KC;
        const uint32_t base = sbase + s * (STG * 4);
#pragma unroll
        for (int i = 0; i < 2; i++) {
            int idx = t + i * 256;
            int row = idx >> 2;
            int q   = idx & 3;
            uint32_t soff = (uint32_t)(row * STRIDE + SWQ(row, q) * 4) * 4;
            int ar = rowBase + row;
            int ok = (ar < M) ? 16 : 0;
            int arc = (ar < M) ? ar : 0;
            size_t ga = (size_t)arc * FIN + k0 + q * 8;
            cp16(base + O_AHI * 4 + soff, Ahi + ga, ok);
            cp16(base + O_ALO * 4 + soff, Alo + ga, ok);
        }
#pragma unroll
        for (int i = 0; i < NTI / 2; i++) {
            int idx = t + i * 256;
            int row = idx >> 2;
            int q   = idx & 3;
            uint32_t soff = (uint32_t)(row * STRIDE + SWQ(row, q) * 4) * 4;
            int br = colBase + row;
            int okb = (br < Nn) ? 16 : 0;
            int brc = (br < Nn) ? br : 0;
            size_t gb = (size_t)brc * FIN + k0 + q * 8;
            cp16(base + O_BHI * 4 + soff, BThi + gb, okb);
            cp16(base + O_BLO * 4 + soff, BTlo + gb, okb);
        }
        asm volatile("cp.async.commit_group;");
    };

    float acc[4][NTI][4];
#pragma unroll
    for (int mt = 0; mt < 4; mt++)
#pragma unroll
        for (int nt = 0; nt < NTI; nt++)
#pragma unroll
            for (int r = 0; r < 4; r++) acc[mt][nt][r] = 0.f;

    issue(0, 0);
    issue(1, 1);

    for (int c = 0; c < NCHUNK; c++) {
        asm volatile("cp.async.wait_group 1;");
        __syncthreads();

        if (c + 2 < NCHUNK) issue(c + 2, (c + 2) % NSTAGE);

        const uint32_t sb = sbase + (c % NSTAGE) * (STG * 4);

#pragma unroll
        for (int ks = 0; ks < 2; ks++) {
            uint32_t ah[4][4], al[4][4];
#pragma unroll
            for (int mt = 0; mt < 4; mt++) {
                int ra_row = warpM * 64 + mt * 16 + a_row;
                int chunk  = ks * 2 + a_kh;
                uint32_t ra = sb + O_AHI * 4 +
                    (uint32_t)(ra_row * STRIDE + SWQ(ra_row, chunk) * 4) * 4;
                ldm_x4(ah[mt][0], ah[mt][1], ah[mt][2], ah[mt][3], ra);
                ldm_x4(al[mt][0], al[mt][1], al[mt][2], al[mt][3],
                       ra + (O_ALO - O_AHI) * 4);
            }
            uint32_t bh[NTI][2], bl[NTI][2];
#pragma unroll
            for (int ntp = 0; ntp < NTI / 2; ntp++) {
                int rb_row = warpN * (NTI * 8) + ntp * 16 + b_row;
                int chunk  = ks * 2 + b_kh;
                uint32_t rb = sb + O_BHI * 4 +
                    (uint32_t)(rb_row * STRIDE + SWQ(rb_row, chunk) * 4) * 4;
                ldm_x4(bh[2 * ntp][0], bh[2 * ntp][1],
                       bh[2 * ntp + 1][0], bh[2 * ntp + 1][1], rb);
                ldm_x4(bl[2 * ntp][0], bl[2 * ntp][1],
                       bl[2 * ntp + 1][0], bl[2 * ntp + 1][1],
                       rb + (O_BLO - O_BHI) * 4);
            }
#pragma unroll
            for (int term = 0; term < 3; term++) {
#pragma unroll
                for (int nt = 0; nt < NTI; nt++) {
#pragma unroll
                    for (int mt = 0; mt < 4; mt++) {
                        float* cc = acc[mt][nt];
                        const uint32_t* aa = (term == 2) ? al[mt] : ah[mt];
                        const uint32_t* bb = (term == 1) ? bl[nt] : bh[nt];
                        mma_bf16(cc[0], cc[1], cc[2], cc[3],
                                 aa[0], aa[1], aa[2], aa[3], bb[0], bb[1]);
                    }
                }
            }
        }
    }

    float* Cuse = C;
    int coff = 0;
    if (splitN > 0 && colBase >= splitN) { Cuse = Cb; coff = splitN; }

#pragma unroll
    for (int mt = 0; mt < 4; mt++) {
        int r0 = rowBase + warpM * 64 + mt * 16 + gid;
        int r1 = r0 + 8;
#pragma unroll
        for (int nt = 0; nt < NTI; nt++) {
            int cb = colBase + warpN * (NTI * 8) + nt * 8 + tg * 2;
            if (cb >= Nn) continue;
            float b0 = bias[cb], b1 = bias[cb + 1];
            int cc = cb - coff;
            if (r0 < M) {
                float2 o = make_float2(acc[mt][nt][0] + b0, acc[mt][nt][1] + b1);
                *(float2*)(Cuse + (size_t)r0 * ldC + cc) = o;
            }
            if (r1 < M) {
                float2 o = make_float2(acc[mt][nt][2] + b0, acc[mt][nt][3] + b1);
                *(float2*)(Cuse + (size_t)r1 * ldC + cc) = o;
            }
        }
    }
}

// ------------------------- CSR scan + scatter --------------------------------
// warp-shuffle scan: 3 barriers per 1024-chunk (was ~20)
__global__ __launch_bounds__(1024) void k_scan()
{
    __shared__ int wsum[32];
    __shared__ int carry;
    int tid  = threadIdx.x;
    int lane = tid & 31;
    int wid  = tid >> 5;
    if (tid == 0) carry = 0;
    __syncthreads();
    for (int base = 0; base < NNODES; base += 1024) {
        int i = base + tid;
        int v = (i < NNODES) ? g_count[i] : 0;
        int s = v;
#pragma unroll
        for (int off = 1; off < 32; off <<= 1) {
            int t2 = __shfl_up_sync(0xFFFFFFFFu, s, off);
            if (lane >= off) s += t2;
        }
        if (lane == 31) wsum[wid] = s;
        __syncthreads();
        if (wid == 0) {
            int ws = wsum[lane];
#pragma unroll
            for (int off = 1; off < 32; off <<= 1) {
                int t2 = __shfl_up_sync(0xFFFFFFFFu, ws, off);
                if (lane >= off) ws += t2;
            }
            wsum[lane] = ws;
        }
        __syncthreads();
        int excl = carry + (wid ? wsum[wid - 1] : 0) + s - v;
        if (i < NNODES) { g_rowstart[i] = excl; g_cursor[i] = excl; }
        int total = wsum[31];
        __syncthreads();           // all reads of wsum/carry done
        if (tid == 0) carry += total;
        __syncthreads();
    }
    if (threadIdx.x == 0) g_rowstart[NNODES] = carry;
}

__global__ void k_scatter(const int* __restrict__ ei)
{
    int e = blockIdx.x * blockDim.x + threadIdx.x;
    if (e >= ET) return;
    int src, dst;
    if (e < NEDGES) { src = ei[2 * e]; dst = ei[2 * e + 1]; }
    else            { src = dst = e - NEDGES; }
    int pos = atomicAdd(&g_cursor[dst], 1);
    g_csr[pos] = src;
}

// ------------------------- fused scores + softmax + aggregate ---------------
// single-read-per-edge + prefetch; ONE barrier per edge (double-buffered red)
__global__ __launch_bounds__(128) void node_fused(
    const float* __restrict__ att, const float* __restrict__ bias)
{
    __shared__ float4 satt[HC / 4];      // 12 KB
    __shared__ float  red[2][4][NH];

    const int node = blockIdx.x;
    const int t = threadIdx.x;
    const int w = t >> 5;
    const int lane = t & 31;

    for (int i = t; i < HC / 4; i += 128)
        satt[i] = ((const float4*)att)[i];

    const int beg = g_rowstart[node];
    const int end = g_rowstart[node + 1];

    float4 xr[NH][2];
    {
        const float4* xrp = (const float4*)(g_xr + (size_t)node * HC);
#pragma unroll
        for (int h = 0; h < NH; h++)
#pragma unroll
            for (int q = 0; q < 2; q++)
                xr[h][q] = xrp[h * 256 + t + 128 * q];
    }
    __syncthreads();

    float m[NH], d[NH];
    float4 acc[NH][2];
#pragma unroll
    for (int h = 0; h < NH; h++) {
        m[h] = -3.0e38f;
        d[h] = 0.f;
#pragma unroll
        for (int q = 0; q < 2; q++) acc[h][q] = make_float4(0.f, 0.f, 0.f, 0.f);
    }

    float4 cur[NH][2];
    if (beg < end) {
        const float4* xlp = (const float4*)(g_xl + (size_t)g_csr[beg] * HC);
#pragma unroll
        for (int h = 0; h < NH; h++)
#pragma unroll
            for (int q = 0; q < 2; q++)
                cur[h][q] = xlp[h * 256 + t + 128 * q];
    }

    int pb = 0;
    for (int p = beg; p < end; p++) {
        float4 nxt[NH][2];
        if (p + 1 < end) {
            const float4* xln = (const float4*)(g_xl + (size_t)g_csr[p + 1] * HC);
#pragma unroll
            for (int h = 0; h < NH; h++)
#pragma unroll
                for (int q = 0; q < 2; q++)
                    nxt[h][q] = xln[h * 256 + t + 128 * q];
        }

        float part[NH];
#pragma unroll
        for (int h = 0; h < NH; h++) {
            part[h] = 0.f;
#pragma unroll
            for (int q = 0; q < 2; q++) {
                float4 v = cur[h][q];
                float4 r = xr[h][q];
                float4 a = satt[h * 256 + t + 128 * q];
                float sx = v.x + r.x; sx = sx > 0.f ? sx : 0.2f * sx;
                float sy = v.y + r.y; sy = sy > 0.f ? sy : 0.2f * sy;
                float sz = v.z + r.z; sz = sz > 0.f ? sz : 0.2f * sz;
                float sw = v.w + r.w; sw = sw > 0.f ? sw : 0.2f * sw;
                part[h] += sx * a.x + sy * a.y + sz * a.z + sw * a.w;
            }
        }
#pragma unroll
        for (int off = 16; off; off >>= 1)
#pragma unroll
            for (int h = 0; h < NH; h++)
                part[h] += __shfl_xor_sync(0xFFFFFFFFu, part[h], off);
        if (lane == 0)
#pragma unroll
            for (int h = 0; h < NH; h++) red[pb][w][h] = part[h];
        __syncthreads();   // ONLY barrier this edge; next edge uses other buf

        float s[NH];
#pragma unroll
        for (int h = 0; h < NH; h++)
            s[h] = red[pb][0][h] + red[pb][1][h] + red[pb][2][h] + red[pb][3][h];
        pb ^= 1;

#pragma unroll
        for (int h = 0; h < NH; h++) {
            float e;
            if (s[h] > m[h]) {
                float sc = __expf(m[h] - s[h]);
                d[h] *= sc;
#pragma unroll
                for (int q = 0; q < 2; q++) {
                    acc[h][q].x *= sc; acc[h][q].y *= sc;
                    acc[h][q].z *= sc; acc[h][q].w *= sc;
                }
                m[h] = s[h];
                e = 1.f;
            } else {
                e = __expf(s[h] - m[h]);
            }
            d[h] += e;
#pragma unroll
            for (int q = 0; q < 2; q++) {
                acc[h][q].x += e * cur[h][q].x;
                acc[h][q].y += e * cur[h][q].y;
                acc[h][q].z += e * cur[h][q].z;
                acc[h][q].w += e * cur[h][q].w;
            }
        }

        if (p + 1 < end) {
#pragma unroll
            for (int h = 0; h < NH; h++)
#pragma unroll
                for (int q = 0; q < 2; q++)
                    cur[h][q] = nxt[h][q];
        }
    }

    float invd[NH];
#pragma unroll
    for (int h = 0; h < NH; h++) invd[h] = 1.f / (d[h] + 1e-16f);

    const float inv3 = 1.0f / 3.0f;
#pragma unroll
    for (int q = 0; q < 2; q++) {
        int f = t + 128 * q;
        float o[4];
        o[0] = (acc[0][q].x * invd[0] + acc[1][q].x * invd[1] + acc[2][q].x * invd[2]) * inv3 + bias[4 * f + 0];
        o[1] = (acc[0][q].y * invd[0] + acc[1][q].y * invd[1] + acc[2][q].y * invd[2]) * inv3 + bias[4 * f + 1];
        o[2] = (acc[0][q].z * invd[0] + acc[1][q].z * invd[1] + acc[2][q].z * invd[2]) * inv3 + bias[4 * f + 2];
        o[3] = (acc[0][q].w * invd[0] + acc[1][q].w * invd[1] + acc[2][q].w * invd[2]) * inv3 + bias[4 * f + 3];
        __nv_bfloat16 hi[4], lo[4];
#pragma unroll
        for (int j = 0; j < 4; j++) {
            hi[j] = __float2bfloat16_rn(o[j]);
            lo[j] = __float2bfloat16_rn(o[j] - __bfloat162float(hi[j]));
        }
        size_t idx = (size_t)node * CH + 4 * f;
        *(uint2*)(g_hmhi + idx) = *(uint2*)hi;
        *(uint2*)(g_hmlo + idx) = *(uint2*)lo;
    }
}

// ------------------------- pass-through copies (single launch) ---------------
__global__ void k_copy_both(const float4* __restrict__ s1, float4* __restrict__ d1,
                            int n1, const float4* __restrict__ s2,
                            float4* __restrict__ d2, int n2)
{
    int i = blockIdx.x * blockDim.x + threadIdx.x;
    if (i < n1) d1[i] = s1[i];
    else if (i < n1 + n2) d2[i - n1] = s2[i - n1];
}

// ------------------------- launch ------------------------------------------
extern "C" void kernel_launch(void* const* d_in, const int* in_sizes, int n_in,
                              void* d_out, int out_size)
{
    const float* x    = (const float*)d_in[0];
    const int*   ei   = (const int*)d_in[1];
    const float* Wl   = (const float*)d_in[2];
    const float* bl   = (const float*)d_in[3];
    const float* Wr   = (const float*)d_in[4];
    const float* br   = (const float*)d_in[5];
    const float* att  = (const float*)d_in[6];
    const float* bias = (const float*)d_in[7];
    const float* Wfc  = (const float*)d_in[8];
    const float* bfc  = (const float*)d_in[9];
    const float* exps   = (const float*)d_in[10];
    const float* exps_c = (const float*)d_in[11];
    float* out = (float*)d_out;

    constexpr int SMEM4 = NSTAGE * (2 * 128 * STRIDE + 2 * 128 * STRIDE) * 4; // 98304
    constexpr int SMEM2 = NSTAGE * (2 * 128 * STRIDE + 2 * 64 * STRIDE) * 4;  // 73728
    cudaFuncSetAttribute(gemm_mma<4>, cudaFuncAttributeMaxDynamicSharedMemorySize,
                         SMEM4);
    cudaFuncSetAttribute(gemm_mma<2>, cudaFuncAttributeMaxDynamicSharedMemorySize,
                         SMEM2);

    // device addresses (NOT host shadow symbols — GB300 ATS trap)
    float *pxl, *pxr, *pbcat;
    __nv_bfloat16 *pxhi, *pxlo, *pwThi, *pwTlo;
    __nv_bfloat16 *phmhi, *phmlo, *pfcThi, *pfcTlo;
    cudaGetSymbolAddress((void**)&pxl,    g_xl);
    cudaGetSymbolAddress((void**)&pxr,    g_xr);
    cudaGetSymbolAddress((void**)&pbcat,  g_bcat);
    cudaGetSymbolAddress((void**)&pxhi,   g_xhi);
    cudaGetSymbolAddress((void**)&pxlo,   g_xlo);
    cudaGetSymbolAddress((void**)&pwThi,  g_wThi);
    cudaGetSymbolAddress((void**)&pwTlo,  g_wTlo);
    cudaGetSymbolAddress((void**)&phmhi,  g_hmhi);
    cudaGetSymbolAddress((void**)&phmlo,  g_hmlo);
    cudaGetSymbolAddress((void**)&pfcThi, g_wfcThi);
    cudaGetSymbolAddress((void**)&pfcTlo, g_wfcTlo);

    // #1: x split + bias concat + zero CSR counts
    x_split<<<(NNODES * FIN + 255) / 256, 256>>>(x, bl, br);
    // #2: Wl split + CSR degree count (zeroing done in #1, stream-ordered)
    // #3: Wr split
    {
        dim3 grid(HC / 32, FIN / 32);
        w_splitT_g<<<grid, 256>>>(Wl, pwThi, pwTlo, HC, FIN, ei);
        w_splitT_g<<<grid, 256>>>(Wr, pwThi + (size_t)HC * FIN,
                                      pwTlo + (size_t)HC * FIN, HC, FIN, nullptr);
    }

    // #4: BOTH projections in ONE launch (profiled slot)
    {
        dim3 grid((2 * HC) / 128, (NNODES + 127) / 128);
        gemm_mma<4><<<grid, 256, SMEM4>>>(pxhi, pxlo, pwThi, pwTlo,
                                          pbcat, pxl, pxr, HC,
                                          NNODES, 2 * HC, HC);
    }

    // CSR prefix + scatter
    k_scan<<<1, 1024>>>();
    k_scatter<<<(ET + 255) / 256, 256>>>(ei);

    // fused scores + online softmax + aggregation + head mean + bias
    node_fused<<<NNODES, 128>>>(att, bias);

    // fc weight split + fc readout
    {
        dim3 grid((NCLS + 31) / 32, CH / 32);
        w_splitT_g<<<grid, 256>>>(Wfc, pfcThi, pfcTlo, NCLS, CH, nullptr);
    }
    {
        dim3 grid((NCLS + 63) / 64, (NNODES + 127) / 128);
        gemm_mma<2><<<grid, 256, SMEM2>>>(phmhi, phmlo, pfcThi, pfcTlo,
                                          bfc, out, nullptr, 0,
                                          NNODES, NCLS, NCLS);
    }

    // pass-through outputs (one launch)
    size_t hElems = (size_t)NNODES * NCLS;
    int n4a = in_sizes[10] / 4;
    int n4b = in_sizes[11] / 4;
    k_copy_both<<<(n4a + n4b + 255) / 256, 256>>>(
        (const float4*)exps, (float4*)(out + hElems), n4a,
        (const float4*)exps_c, (float4*)(out + hElems + in_sizes[10]), n4b);
}